// round 13
// baseline (speedup 1.0000x reference)
#include <cuda_runtime.h>
#include <cuda_bf16.h>
#include <cuda_fp8.h>
#include <cstdint>

#define BATCH 4096
#define IN_DIM 16
#define LEVELS 17
#define ODIM 5
#define HDIM 1024
#define HS 3
#define KP 128
#define TOTW (ODIM*LEVELS)
#define HN (BATCH*HDIM)
#define WI ((size_t)KP*HDIM)
#define WB ((size_t)HDIM*HDIM)
// fp8 scales: A-side pairs with B-side so products land at scale 1
#define SAF 0.0009765625f  /* 2^-10: a8 = e5m2(v*SAF)   */
#define SAL 16.0f          /* 2^4  : al8= e4m3(lo*SAL)  */
#define SBF 0.0625f        /* 2^-4 : w8 = e5m2(v*SBF)   */
#define SBL 1024.0f        /* 2^10 : wl8= e4m3(lo*SBL)  */

__device__ __nv_bfloat16 g_hhi[4ull*HN];
__device__ uint8_t g_h8[4ull*HN], g_hl8[4ull*HN];
__device__ __nv_bfloat16 g_phi[2ull*BATCH*KP];
__device__ uint8_t g_p8[2ull*BATCH*KP], g_pl8[2ull*BATCH*KP];
__device__ __nv_bfloat16 g_wphi[34ull*WI], g_wplo[34ull*WI];
__device__ __nv_bfloat16 g_wchi[34ull*WI];
__device__ uint8_t g_wc8[34ull*WI], g_wcl8[34ull*WI];
__device__ __nv_bfloat16 g_wbhi[3ull*WB], g_wblo[3ull*WB];
__device__ uint8_t g_wb8[3ull*WB], g_wbl8[3ull*WB];
__device__ float g_bcomb[34ull*HDIM];
__device__ float g_tot[2ull*BATCH*TOTW];

__device__ __forceinline__ uint32_t smem_u32(const void* p){ return (uint32_t)__cvta_generic_to_shared(p); }
__device__ __forceinline__ void cpa16(uint32_t d, const void* s){
    asm volatile("cp.async.cg.shared.global [%0], [%1], 16;" :: "r"(d),"l"(s)); }
#define CP_COMMIT() asm volatile("cp.async.commit_group;" ::: "memory")
__device__ __forceinline__ void ldsm4(uint32_t* r, uint32_t a){
    asm volatile("ldmatrix.sync.aligned.m8n8.x4.shared.b16 {%0,%1,%2,%3}, [%4];"
        : "=r"(r[0]),"=r"(r[1]),"=r"(r[2]),"=r"(r[3]) : "r"(a));
}
__device__ __forceinline__ void mma_bf16(float* d, const uint32_t* a, const uint32_t* b){
    asm("mma.sync.aligned.m16n8k16.row.col.f32.bf16.bf16.f32 "
        "{%0,%1,%2,%3}, {%4,%5,%6,%7}, {%8,%9}, {%0,%1,%2,%3};"
        : "+f"(d[0]),"+f"(d[1]),"+f"(d[2]),"+f"(d[3])
        : "r"(a[0]),"r"(a[1]),"r"(a[2]),"r"(a[3]), "r"(b[0]),"r"(b[1]));
}
__device__ __forceinline__ void mma_e5e4(float* d, const uint32_t* a, const uint32_t* b){
    asm("mma.sync.aligned.m16n8k32.row.col.f32.e5m2.e4m3.f32 "
        "{%0,%1,%2,%3}, {%4,%5,%6,%7}, {%8,%9}, {%0,%1,%2,%3};"
        : "+f"(d[0]),"+f"(d[1]),"+f"(d[2]),"+f"(d[3])
        : "r"(a[0]),"r"(a[1]),"r"(a[2]),"r"(a[3]), "r"(b[0]),"r"(b[1]));
}
__device__ __forceinline__ void mma_e4e5(float* d, const uint32_t* a, const uint32_t* b){
    asm("mma.sync.aligned.m16n8k32.row.col.f32.e4m3.e5m2.f32 "
        "{%0,%1,%2,%3}, {%4,%5,%6,%7}, {%8,%9}, {%0,%1,%2,%3};"
        : "+f"(d[0]),"+f"(d[1]),"+f"(d[2]),"+f"(d[3])
        : "r"(a[0]),"r"(a[1]),"r"(a[2]),"r"(a[3]), "r"(b[0]),"r"(b[1]));
}
__device__ __forceinline__ uint16_t cvt_e5m2x2(float hi, float lo){ uint16_t r;
    asm("cvt.rn.satfinite.e5m2x2.f32 %0, %1, %2;" : "=h"(r) : "f"(hi), "f"(lo)); return r; }
__device__ __forceinline__ uint16_t cvt_e4m3x2(float hi, float lo){ uint16_t r;
    asm("cvt.rn.satfinite.e4m3x2.f32 %0, %1, %2;" : "=h"(r) : "f"(hi), "f"(lo)); return r; }
__device__ __forceinline__ float e4m3f(uint8_t b){
    __half_raw hr = __nv_cvt_fp8_to_halfraw((__nv_fp8_storage_t)b, __NV_E4M3);
    return __half2float(*reinterpret_cast<__half*>(&hr)); }

#define STG_SZ 32768
#define SMEM_DYN (3*STG_SZ)

// ===== MAIN GEMM: bf16 main pass + fp8 corrections =====
// stage smem: Ahi(8K) | Apack[a8|al8](8K) | Bhi(8K) | Bpack[wl8|w8](8K)
__global__ void __launch_bounds__(256, 2)
gemm_fp8(const __nv_bfloat16* __restrict__ Ah, const uint8_t* __restrict__ A8,
         const uint8_t* __restrict__ Al8, int AKD,
         const __nv_bfloat16* __restrict__ Bh, const uint8_t* __restrict__ B8,
         const uint8_t* __restrict__ Bl8, const float* __restrict__ bias,
         __nv_bfloat16* __restrict__ oH, uint8_t* __restrict__ o8, uint8_t* __restrict__ ol8,
         int K, int relu)
{
    extern __shared__ char smem[];
    __shared__ float sbias[128];
    const int tid=threadIdx.x, wid=tid>>5, lane=tid&31;
    const int Nbase=blockIdx.x*128, Mbase=blockIdx.y*128;
    const int warpM=wid&1, warpN=wid>>1;
    if(tid<128) sbias[tid]=bias[Nbase+tid];
    const uint32_t sbase=smem_u32(smem);

    auto load_stage=[&](int s){
        const uint32_t sb = sbase + (uint32_t)(s%3)*STG_SZ;
        const int kb = s*32;
        #pragma unroll
        for(int i=0;i<2;++i){
            int idx=tid+i*256, r=idx>>2, c=idx&3;
            uint32_t off=(uint32_t)(r*64 + ((c ^ ((r>>1)&3))*16));
            size_t ra=(size_t)(Mbase+r)*AKD+kb, rb=(size_t)(Nbase+r)*AKD+kb;
            cpa16(sb+off,        Ah+ra+c*8);
            cpa16(sb+8192+off,   c<2 ? (const void*)(A8+ra+c*16)  : (const void*)(Al8+ra+(c-2)*16));
            cpa16(sb+16384+off,  Bh+rb+c*8);
            cpa16(sb+24576+off,  c<2 ? (const void*)(Bl8+rb+c*16) : (const void*)(B8+rb+(c-2)*16));
        }
        CP_COMMIT();
    };

    float acc[4][4][4];
    #pragma unroll
    for(int m=0;m<4;++m)
        #pragma unroll
        for(int n=0;n<4;++n){acc[m][n][0]=0;acc[m][n][1]=0;acc[m][n][2]=0;acc[m][n][3]=0;}

    const int NS=K>>5;
    load_stage(0); load_stage(1);

    for(int s=0;s<NS;++s){
        if(s+1<NS) asm volatile("cp.async.wait_group 1;":::"memory");
        else       asm volatile("cp.async.wait_group 0;":::"memory");
        __syncthreads();
        if(s+2<NS) load_stage(s+2);
        const uint32_t sb = sbase + (uint32_t)(s%3)*STG_SZ;

        // bf16 B frags (2 k16-slices)
        uint32_t bhf[2][4][2];
        #pragma unroll
        for(int ks=0;ks<2;++ks){
            #pragma unroll
            for(int ntp=0;ntp<2;++ntp){
                int grp=lane>>3, tile=ntp*2+(grp>>1);
                int n=warpN*32+tile*8+(lane&7);
                int cc=(ks*2+(grp&1))^((n>>1)&3);
                uint32_t t[4];
                ldsm4(t, sb+16384u+(uint32_t)(n*64+cc*16));
                bhf[ks][2*ntp][0]=t[0]; bhf[ks][2*ntp][1]=t[1];
                bhf[ks][2*ntp+1][0]=t[2]; bhf[ks][2*ntp+1][1]=t[3];
            }
        }
        // fp8 B frags (k32): wl8 = chunks {0,1}, w8 = chunks {2,3}
        uint32_t bl8[4][2], b8[4][2];
        #pragma unroll
        for(int g=0; g<2; ++g){
            int n = warpN*32 + g*16 + (((lane>>4)<<3)|(lane&7));
            int sw=(n>>1)&3;
            int cl = (lane>>3)&1;
            uint32_t t[4];
            ldsm4(t, sb+24576u+(uint32_t)(n*64+((cl^sw)*16)));
            bl8[2*g][0]=t[0]; bl8[2*g][1]=t[1]; bl8[2*g+1][0]=t[2]; bl8[2*g+1][1]=t[3];
            ldsm4(t, sb+24576u+(uint32_t)(n*64+(((2+cl)^sw)*16)));
            b8[2*g][0]=t[0]; b8[2*g][1]=t[1]; b8[2*g+1][0]=t[2]; b8[2*g+1][1]=t[3];
        }
        #pragma unroll
        for(int mt=0;mt<4;++mt){
            int r=warpM*64+mt*16+(lane&15);
            int sw=(r>>1)&3, hc=lane>>4;
            uint32_t ah0[4],ah1[4],a8f[4],al8f[4];
            ldsm4(ah0, sb+(uint32_t)(r*64+((hc^sw)*16)));
            ldsm4(ah1, sb+(uint32_t)(r*64+(((2+hc)^sw)*16)));
            ldsm4(a8f, sb+8192u+(uint32_t)(r*64+((hc^sw)*16)));
            ldsm4(al8f,sb+8192u+(uint32_t)(r*64+(((2+hc)^sw)*16)));
            #pragma unroll
            for(int nt=0;nt<4;++nt) mma_bf16(acc[mt][nt], ah0, bhf[0][nt]);
            #pragma unroll
            for(int nt=0;nt<4;++nt) mma_bf16(acc[mt][nt], ah1, bhf[1][nt]);
            #pragma unroll
            for(int nt=0;nt<4;++nt) mma_e5e4(acc[mt][nt], a8f, bl8[nt]);   // A * Wlo
            #pragma unroll
            for(int nt=0;nt<4;++nt) mma_e4e5(acc[mt][nt], al8f, b8[nt]);   // Alo * W
        }
    }
    #pragma unroll
    for(int mt=0;mt<4;++mt){
        #pragma unroll
        for(int nt=0;nt<4;++nt){
            int rl=warpM*64+mt*16+(lane>>2);
            int cl=warpN*32+nt*8+(lane&3)*2;
            #pragma unroll
            for(int h=0;h<2;++h){
                int row=Mbase+rl+h*8;
                float v0=acc[mt][nt][2*h]  +sbias[cl];
                float v1=acc[mt][nt][2*h+1]+sbias[cl+1];
                if(relu){ v0=fmaxf(v0,0.f); v1=fmaxf(v1,0.f); }
                __nv_bfloat16 h0=__float2bfloat16(v0), h1=__float2bfloat16(v1);
                __nv_bfloat162 hv; hv.x=h0; hv.y=h1;
                float l0=v0-__bfloat162float(h0), l1=v1-__bfloat162float(h1);
                size_t o=(size_t)row*HDIM+Nbase+cl;
                *reinterpret_cast<uint32_t*>(oH+o)=*reinterpret_cast<uint32_t*>(&hv);
                *reinterpret_cast<uint16_t*>(o8+o) =cvt_e5m2x2(v1*SAF, v0*SAF);
                *reinterpret_cast<uint16_t*>(ol8+o)=cvt_e4m3x2(l1*SAL, l0*SAL);
            }
        }
    }
}

// ===== PRECOMPUTE GEMM (bf16x3): WcombT = WblkT0 @ WinPad^T, emits B-variant fp8 =====
__global__ void __launch_bounds__(256, 2)
gemm_pre(const __nv_bfloat16* __restrict__ Ah, const __nv_bfloat16* __restrict__ Al, int AKD,
         const __nv_bfloat16* __restrict__ Bh, const __nv_bfloat16* __restrict__ Bl, size_t bZ,
         __nv_bfloat16* __restrict__ oH, uint8_t* __restrict__ o8, uint8_t* __restrict__ ol8,
         size_t oZ, int ldo, int K)
{
    extern __shared__ char smem[];
    const int tid=threadIdx.x, wid=tid>>5, lane=tid&31;
    const size_t z=blockIdx.z;
    Bh+=z*bZ; Bl+=z*bZ; oH+=z*oZ; o8+=z*oZ; ol8+=z*oZ;
    const int Nbase=blockIdx.x*128, Mbase=blockIdx.y*128;
    const int warpM=wid&1, warpN=wid>>1;
    const uint32_t sbase=smem_u32(smem);

    auto load_stage=[&](int s){
        const uint32_t sb=sbase+(uint32_t)(s%3)*STG_SZ;
        const int kb=s*32;
        #pragma unroll
        for(int i=0;i<2;++i){
            int idx=tid+i*256, r=idx>>2, c=idx&3;
            uint32_t off=(uint32_t)(r*64+((c^((r>>1)&3))*16));
            size_t ga=(size_t)(Mbase+r)*AKD+kb+c*8, gb=(size_t)(Nbase+r)*AKD+kb+c*8;
            cpa16(sb+off,Ah+ga); cpa16(sb+8192+off,Al+ga);
            cpa16(sb+16384+off,Bh+gb); cpa16(sb+24576+off,Bl+gb);
        }
        CP_COMMIT();
    };
    float acc[4][4][4];
    #pragma unroll
    for(int m=0;m<4;++m)
        #pragma unroll
        for(int n=0;n<4;++n){acc[m][n][0]=0;acc[m][n][1]=0;acc[m][n][2]=0;acc[m][n][3]=0;}
    const int NS=K>>5;
    load_stage(0); load_stage(1);
    for(int s=0;s<NS;++s){
        if(s+1<NS) asm volatile("cp.async.wait_group 1;":::"memory");
        else       asm volatile("cp.async.wait_group 0;":::"memory");
        __syncthreads();
        if(s+2<NS) load_stage(s+2);
        const uint32_t sb=sbase+(uint32_t)(s%3)*STG_SZ;
        uint32_t bf[2][2][4][2];
        #pragma unroll
        for(int ks=0;ks<2;++ks)
            #pragma unroll
            for(int ntp=0;ntp<2;++ntp){
                int grp=lane>>3, tile=ntp*2+(grp>>1);
                int n=warpN*32+tile*8+(lane&7);
                int cc=(ks*2+(grp&1))^((n>>1)&3);
                uint32_t t[4];
                ldsm4(t, sb+16384u+(uint32_t)(n*64+cc*16));
                bf[ks][0][2*ntp][0]=t[0]; bf[ks][0][2*ntp][1]=t[1];
                bf[ks][0][2*ntp+1][0]=t[2]; bf[ks][0][2*ntp+1][1]=t[3];
                ldsm4(t, sb+24576u+(uint32_t)(n*64+cc*16));
                bf[ks][1][2*ntp][0]=t[0]; bf[ks][1][2*ntp][1]=t[1];
                bf[ks][1][2*ntp+1][0]=t[2]; bf[ks][1][2*ntp+1][1]=t[3];
            }
        #pragma unroll
        for(int idx=0; idx<8; ++idx){
            int ks=idx>>2, mt=idx&3;
            int r=warpM*64+mt*16+(lane&15);
            int cc=(ks*2+(lane>>4))^((r>>1)&3);
            uint32_t a0[4],a1[4];
            ldsm4(a0, sb+(uint32_t)(r*64+cc*16));
            ldsm4(a1, sb+8192u+(uint32_t)(r*64+cc*16));
            #pragma unroll
            for(int nt=0;nt<4;++nt) mma_bf16(acc[mt][nt], a0, bf[ks][0][nt]);
            #pragma unroll
            for(int nt=0;nt<4;++nt) mma_bf16(acc[mt][nt], a0, bf[ks][1][nt]);
            #pragma unroll
            for(int nt=0;nt<4;++nt) mma_bf16(acc[mt][nt], a1, bf[ks][0][nt]);
        }
    }
    #pragma unroll
    for(int mt=0;mt<4;++mt)
        #pragma unroll
        for(int nt=0;nt<4;++nt){
            int rl=warpM*64+mt*16+(lane>>2);
            int cl=warpN*32+nt*8+(lane&3)*2;
            #pragma unroll
            for(int h=0;h<2;++h){
                int row=Mbase+rl+h*8;
                float v0=acc[mt][nt][2*h], v1=acc[mt][nt][2*h+1];
                __nv_bfloat16 h0=__float2bfloat16(v0), h1=__float2bfloat16(v1);
                __nv_bfloat162 hv; hv.x=h0; hv.y=h1;
                float l0=v0-__bfloat162float(h0), l1=v1-__bfloat162float(h1);
                size_t o=(size_t)row*ldo+Nbase+cl;
                *reinterpret_cast<uint32_t*>(oH+o)=*reinterpret_cast<uint32_t*>(&hv);
                *reinterpret_cast<uint16_t*>(o8+o) =cvt_e5m2x2(v1*SBF, v0*SBF);
                *reinterpret_cast<uint16_t*>(ol8+o)=cvt_e4m3x2(l1*SBL, l0*SBL);
            }
        }
}

// ---- WblkT: transpose + bf16 hi/lo + B-variant fp8 ----
__global__ void transpose_split(const float* __restrict__ src,
                                __nv_bfloat16* __restrict__ dH, __nv_bfloat16* __restrict__ dL,
                                uint8_t* __restrict__ d8, uint8_t* __restrict__ dl8)
{
    __shared__ float t[32][33];
    const int mz=blockIdx.z;
    src+=(size_t)mz*WB; dH+=(size_t)mz*WB; dL+=(size_t)mz*WB; d8+=(size_t)mz*WB; dl8+=(size_t)mz*WB;
    const int kt=blockIdx.x*32, nt=blockIdx.y*32, tx=threadIdx.x, ty=threadIdx.y;
    for(int r=ty;r<32;r+=8) t[r][tx]=src[(size_t)(kt+r)*HDIM+nt+tx];
    __syncthreads();
    for(int r=ty;r<32;r+=8){
        int n=nt+r, k=kt+tx;
        float v=t[tx][r]; __nv_bfloat16 h=__float2bfloat16(v);
        float lo=v-__bfloat162float(h);
        size_t o=(size_t)n*HDIM+k;
        dH[o]=h; dL[o]=__float2bfloat16(lo);
        d8[o]=(uint8_t)(cvt_e5m2x2(0.f,v*SBF)&0xFF);
        dl8[o]=(uint8_t)(cvt_e4m3x2(0.f,lo*SBL)&0xFF);
    }
}

// ---- Win pad + bf16 split (precompute B operand) ----
__global__ void split_pad(const float* __restrict__ src,
                          __nv_bfloat16* __restrict__ dH, __nv_bfloat16* __restrict__ dL)
{
    size_t i=(size_t)blockIdx.x*256+threadIdx.x;
    if(i>=17ull*WI) return;
    size_t z=i/WI, rem=i%WI;
    int k=(int)(rem/HDIM), j=(int)(rem%HDIM);
    float v=(k<96)?src[(z*96+k)*HDIM+j]:0.f;
    __nv_bfloat16 h=__float2bfloat16(v);
    dH[i]=h; dL[i]=__float2bfloat16(v-__bfloat162float(h));
}

// ---- bcomb: read Wblk0 once, 34 accumulators ----
__global__ void bcomb_k(const float* __restrict__ bin_f, const float* __restrict__ bin_b,
                        const float* __restrict__ Wblk, const float* __restrict__ bblk,
                        float* __restrict__ bcomb)
{
    int n=blockIdx.x*256+threadIdx.x;
    float acc[34];
    float b0=bblk[n];
    #pragma unroll
    for(int z=0;z<34;++z) acc[z]=b0;
    for(int j=0;j<HDIM;++j){
        float w=Wblk[(size_t)j*HDIM+n];
        #pragma unroll
        for(int z=0;z<17;++z){
            acc[z]   +=bin_f[z*HDIM+j]*w;
            acc[17+z]+=bin_b[z*HDIM+j]*w;
        }
    }
    #pragma unroll
    for(int z=0;z<34;++z) bcomb[(size_t)z*HDIM+n]=acc[z];
}

// ---- init prev (A-variant trio, both dirs) ----
__global__ void init_prev_k(const float* __restrict__ x,
                            __nv_bfloat16* __restrict__ phi, uint8_t* __restrict__ p8,
                            uint8_t* __restrict__ pl8)
{
    int i=blockIdx.x*256+threadIdx.x; if(i>=BATCH*KP) return;
    int b=i>>7, c=i&127;
    float v=(c<IN_DIM)?x[b*IN_DIM+c]:0.f;
    __nv_bfloat16 h=__float2bfloat16(v);
    float lo=v-__bfloat162float(h);
    uint8_t q8=(uint8_t)(cvt_e5m2x2(0.f,v*SAF)&0xFF);
    uint8_t ql=(uint8_t)(cvt_e4m3x2(0.f,lo*SAL)&0xFF);
    size_t o2=(size_t)BATCH*KP;
    phi[i]=h; p8[i]=q8; pl8[i]=ql;
    phi[i+o2]=h; p8[i+o2]=q8; pl8[i+o2]=ql;
}

// ---- out-proj: v = hi + e4m3(lo8)/SAL; writes tot + prev trio ----
__global__ void out_proj(const __nv_bfloat16* __restrict__ hHi, const uint8_t* __restrict__ hL8,
                         const float* __restrict__ Wout, const float* __restrict__ bout,
                         float* __restrict__ tot,
                         __nv_bfloat16* __restrict__ phi, uint8_t* __restrict__ p8,
                         uint8_t* __restrict__ pl8, int level)
{
    const int b=blockIdx.x, tid=threadIdx.x;
    const size_t hoff=(size_t)b*HDIM;
    __shared__ float sh[HDIM];
    #pragma unroll
    for(int q=0;q<4;++q){ int k=tid+q*256;
        sh[k]=__bfloat162float(hHi[hoff+k]) + e4m3f(hL8[hoff+k])*(1.0f/SAL); }
    __syncthreads();
    const int warp=tid>>5, lane=tid&31;
    if(warp<ODIM){
        float acc=0.f;
        for(int k=lane;k<HDIM;k+=32) acc+=sh[k]*Wout[k*ODIM+warp];
        #pragma unroll
        for(int off=16;off>0;off>>=1) acc+=__shfl_down_sync(0xffffffffu,acc,off);
        if(lane==0){
            float val=acc+bout[warp];
            tot[b*TOTW+level*ODIM+warp]=val;
            if(level<LEVELS-1){
                int pc=b*KP+IN_DIM+level*ODIM+warp;
                __nv_bfloat16 h=__float2bfloat16(val);
                float lo=val-__bfloat162float(h);
                phi[pc]=h;
                p8[pc]=(uint8_t)(cvt_e5m2x2(0.f,val*SAF)&0xFF);
                pl8[pc]=(uint8_t)(cvt_e4m3x2(0.f,lo*SAL)&0xFF);
            }
        }
    }
}

// ---- attention + final linear ----
__global__ void attn_final(const float* __restrict__ totbuf,
                           const float* __restrict__ W1, const float* __restrict__ W2,
                           const float* __restrict__ W3, const float* __restrict__ W4,
                           const float* __restrict__ b4, float* __restrict__ out)
{
    const int b=blockIdx.x;
    const float* totF=totbuf; const float* totB=totbuf+(size_t)BATCH*TOTW;
    __shared__ float tf[ODIM][LEVELS], tb[ODIM][LEVELS];
    __shared__ float q[LEVELS][ODIM], kk[ODIM][LEVELS], v[LEVELS][ODIM];
    __shared__ float attn[LEVELS][LEVELS], res[TOTW], w1[25], w2[25], w3[25];
    const int tid=threadIdx.x;
    if(tid<TOTW){
        reinterpret_cast<float*>(tf)[tid]=totF[b*TOTW+tid];
        int d=tid/LEVELS, t=tid%LEVELS;
        tb[d][t]=totB[b*TOTW+d*LEVELS+(LEVELS-1-t)];
    }
    if(tid<25){ w1[tid]=W1[tid]; w2[tid]=W2[tid]; w3[tid]=W3[tid]; }
    __syncthreads();
    if(tid<TOTW){
        int t=tid/ODIM, e=tid%ODIM;
        float sq=0.f,sk=0.f,sv=0.f;
        #pragma unroll
        for(int d=0;d<ODIM;++d){
            sq+=tf[d][t]*w1[d*ODIM+e]; sk+=tb[d][t]*w2[d*ODIM+e]; sv+=tb[d][t]*w3[d*ODIM+e]; }
        q[t][e]=sq; kk[e][t]=sk; v[t][e]=sv;
    }
    __syncthreads();
    for(int idx=tid;idx<LEVELS*LEVELS;idx+=blockDim.x){
        int t=idx/LEVELS, s=idx%LEVELS;
        float sc=0.f;
        #pragma unroll
        for(int e=0;e<ODIM;++e) sc+=q[t][e]*kk[e][s];
        attn[t][s]=sc;
    }
    __syncthreads();
    if(tid<LEVELS){
        int s=tid; float mx=-1e30f;
        for(int t=0;t<LEVELS;++t) mx=fmaxf(mx,attn[t][s]);
        float sm=0.f;
        for(int t=0;t<LEVELS;++t){ float e=expf(attn[t][s]-mx); attn[t][s]=e; sm+=e; }
        float inv=1.f/sm;
        for(int t=0;t<LEVELS;++t) attn[t][s]*=inv;
    }
    __syncthreads();
    if(tid<TOTW){
        int t=tid/ODIM, e=tid%ODIM; float r=0.f;
        for(int s=0;s<LEVELS;++s) r+=attn[t][s]*v[s][e];
        res[tid]=r;
    }
    __syncthreads();
    if(tid<TOTW){
        int o=tid; float y=b4[o];
        for(int j=0;j<TOTW;++j) y+=res[j]*W4[j*TOTW+o];
        out[(size_t)b*TOTW+o]=y;
    }
}

// ---- host ----
extern "C" void kernel_launch(void* const* d_in, const int* in_sizes, int n_in,
                              void* d_out, int out_size)
{
    const float* x=(const float*)d_in[0];
    const float* Win_f=(const float*)d_in[1];  const float* bin_f=(const float*)d_in[2];
    const float* Win_b=(const float*)d_in[3];  const float* bin_b=(const float*)d_in[4];
    const float* Wblk=(const float*)d_in[5];   const float* bblk=(const float*)d_in[6];
    const float* Wout_f=(const float*)d_in[7]; const float* bout_f=(const float*)d_in[8];
    const float* Wout_b=(const float*)d_in[9]; const float* bout_b=(const float*)d_in[10];
    const float* W1=(const float*)d_in[11]; const float* W2=(const float*)d_in[12];
    const float* W3=(const float*)d_in[13]; const float* W4=(const float*)d_in[14];
    const float* b4=(const float*)d_in[15];
    float* out=(float*)d_out;

    __nv_bfloat16 *hhi,*phi,*wphi,*wplo,*wchi,*wbhi,*wblo;
    uint8_t *h8,*hl8,*p8,*pl8,*wc8,*wcl8,*wb8,*wbl8;
    float *tot,*bcomb;
    cudaGetSymbolAddress((void**)&hhi,g_hhi);
    cudaGetSymbolAddress((void**)&h8,g_h8);     cudaGetSymbolAddress((void**)&hl8,g_hl8);
    cudaGetSymbolAddress((void**)&phi,g_phi);
    cudaGetSymbolAddress((void**)&p8,g_p8);     cudaGetSymbolAddress((void**)&pl8,g_pl8);
    cudaGetSymbolAddress((void**)&wphi,g_wphi); cudaGetSymbolAddress((void**)&wplo,g_wplo);
    cudaGetSymbolAddress((void**)&wchi,g_wchi);
    cudaGetSymbolAddress((void**)&wc8,g_wc8);   cudaGetSymbolAddress((void**)&wcl8,g_wcl8);
    cudaGetSymbolAddress((void**)&wbhi,g_wbhi); cudaGetSymbolAddress((void**)&wblo,g_wblo);
    cudaGetSymbolAddress((void**)&wb8,g_wb8);   cudaGetSymbolAddress((void**)&wbl8,g_wbl8);
    cudaGetSymbolAddress((void**)&tot,g_tot);   cudaGetSymbolAddress((void**)&bcomb,g_bcomb);

    cudaFuncSetAttribute(gemm_fp8, cudaFuncAttributeMaxDynamicSharedMemorySize, SMEM_DYN);
    cudaFuncSetAttribute(gemm_pre, cudaFuncAttributeMaxDynamicSharedMemorySize, SMEM_DYN);

    cudaStream_t sB;
    cudaStreamCreateWithFlags(&sB, cudaStreamNonBlocking);
    cudaEvent_t eFork, eJoin;
    cudaEventCreateWithFlags(&eFork, cudaEventDisableTiming);
    cudaEventCreateWithFlags(&eJoin, cudaEventDisableTiming);

    // prep on default stream
    transpose_split<<<dim3(HDIM/32,HDIM/32,HS),dim3(32,8)>>>(Wblk,wbhi,wblo,wb8,wbl8);
    split_pad<<<(int)((17ull*WI+255)/256),256>>>(Win_f, wphi,       wplo);
    split_pad<<<(int)((17ull*WI+255)/256),256>>>(Win_b, wphi+17*WI, wplo+17*WI);
    bcomb_k<<<HDIM/256,256>>>(bin_f,bin_b,Wblk,bblk,bcomb);
    init_prev_k<<<(BATCH*KP+255)/256,256>>>(x,phi,p8,pl8);

    cudaEventRecord(eFork, 0);
    cudaStreamWaitEvent(sB, eFork, 0);

    // WcombT precompute, one direction per stream
    gemm_pre<<<dim3(1,HDIM/128,LEVELS),256,SMEM_DYN,0>>>(
        wbhi, wblo, HDIM, wphi, wplo, WI, wchi, wc8, wcl8, WI, KP, HDIM);
    gemm_pre<<<dim3(1,HDIM/128,LEVELS),256,SMEM_DYN,sB>>>(
        wbhi, wblo, HDIM, wphi+17*WI, wplo+17*WI, WI,
        wchi+17*WI, wc8+17*WI, wcl8+17*WI, WI, KP, HDIM);

    dim3 gg(HDIM/128, BATCH/128, 1);
    const size_t PK=(size_t)BATCH*KP;

    for(int i=0;i<LEVELS;++i){
        gemm_fp8<<<gg,256,SMEM_DYN,0>>>(phi,p8,pl8,KP,
            wchi+(size_t)i*WI, wc8+(size_t)i*WI, wcl8+(size_t)i*WI,
            bcomb+(size_t)i*HDIM, hhi, h8, hl8, KP, 1);
        gemm_fp8<<<gg,256,SMEM_DYN,sB>>>(phi+PK,p8+PK,pl8+PK,KP,
            wchi+(size_t)(17+i)*WI, wc8+(size_t)(17+i)*WI, wcl8+(size_t)(17+i)*WI,
            bcomb+(size_t)(17+i)*HDIM, hhi+2ull*HN, h8+2ull*HN, hl8+2ull*HN, KP, 1);
        int cur=0;
        for(int j=1;j<HS;++j){
            gemm_fp8<<<gg,256,SMEM_DYN,0>>>(
                hhi+(size_t)cur*HN, h8+(size_t)cur*HN, hl8+(size_t)cur*HN, HDIM,
                wbhi+(size_t)j*WB, wb8+(size_t)j*WB, wbl8+(size_t)j*WB,
                bblk+(size_t)j*HDIM,
                hhi+(size_t)(cur^1)*HN, h8+(size_t)(cur^1)*HN, hl8+(size_t)(cur^1)*HN, HDIM, 1);
            gemm_fp8<<<gg,256,SMEM_DYN,sB>>>(
                hhi+(size_t)(2+cur)*HN, h8+(size_t)(2+cur)*HN, hl8+(size_t)(2+cur)*HN, HDIM,
                wbhi+(size_t)j*WB, wb8+(size_t)j*WB, wbl8+(size_t)j*WB,
                bblk+(size_t)j*HDIM,
                hhi+(size_t)(2+(cur^1))*HN, h8+(size_t)(2+(cur^1))*HN, hl8+(size_t)(2+(cur^1))*HN, HDIM, 1);
            cur^=1;
        }
        out_proj<<<dim3(BATCH,1,1),256,0,0>>>(hhi, hl8,
            Wout_f+(size_t)i*HDIM*ODIM, bout_f+i*ODIM, tot, phi, p8, pl8, i);
        out_proj<<<dim3(BATCH,1,1),256,0,sB>>>(hhi+2ull*HN, hl8+2ull*HN,
            Wout_b+(size_t)i*HDIM*ODIM, bout_b+i*ODIM, tot+(size_t)BATCH*TOTW,
            phi+PK, p8+PK, pl8+PK, i);
    }

    cudaEventRecord(eJoin, sB);
    cudaStreamWaitEvent(0, eJoin, 0);
    attn_final<<<BATCH,128>>>(tot,W1,W2,W3,W4,b4,out);
}

// round 14
// speedup vs baseline: 1.4155x; 1.4155x over previous
#include <cuda_runtime.h>
#include <cuda_bf16.h>
#include <cstdint>

#define BATCH 4096
#define IN_DIM 16
#define LEVELS 17
#define ODIM 5
#define HDIM 1024
#define HS 3
#define KP 128
#define TOTW (ODIM*LEVELS)
#define HN (BATCH*HDIM)
#define WI ((size_t)KP*HDIM)
#define WB ((size_t)HDIM*HDIM)

__device__ __nv_bfloat16 g_hhi[4ull*HN], g_hlo[4ull*HN];
__device__ __nv_bfloat16 g_phi[2ull*BATCH*KP], g_plo[2ull*BATCH*KP];
__device__ __nv_bfloat16 g_wphi[34ull*WI], g_wplo[34ull*WI];
__device__ __nv_bfloat16 g_wchi[34ull*WI], g_wclo[34ull*WI];
__device__ __nv_bfloat16 g_wbhi[3ull*WB], g_wblo[3ull*WB];
__device__ float g_bcomb[34ull*HDIM];
__device__ float g_zero[128];
__device__ float g_tot[2ull*BATCH*TOTW];

__device__ __forceinline__ uint32_t smem_u32(const void* p){ return (uint32_t)__cvta_generic_to_shared(p); }
__device__ __forceinline__ void cpa16(uint32_t d, const void* s){
    asm volatile("cp.async.cg.shared.global [%0], [%1], 16;" :: "r"(d),"l"(s)); }
#define CP_COMMIT() asm volatile("cp.async.commit_group;" ::: "memory")
__device__ __forceinline__ void ldsm4(uint32_t* r, uint32_t a){
    asm volatile("ldmatrix.sync.aligned.m8n8.x4.shared.b16 {%0,%1,%2,%3}, [%4];"
        : "=r"(r[0]),"=r"(r[1]),"=r"(r[2]),"=r"(r[3]) : "r"(a));
}
__device__ __forceinline__ void mma16816(float* d, const uint32_t* a, const uint32_t* b){
    asm("mma.sync.aligned.m16n8k16.row.col.f32.bf16.bf16.f32 "
        "{%0,%1,%2,%3}, {%4,%5,%6,%7}, {%8,%9}, {%0,%1,%2,%3};"
        : "+f"(d[0]),"+f"(d[1]),"+f"(d[2]),"+f"(d[3])
        : "r"(a[0]),"r"(a[1]),"r"(a[2]),"r"(a[3]), "r"(b[0]),"r"(b[1]));
}

// GEMM: C = act(A @ B^T + bias). p3=1: full bf16x3 (hi*hi + hi*lo + lo*hi).
// p3=0: bf16x2 (hi*hi + lo*hi) — skips B-lo loads entirely.
#define STG_SZ 32768
#define SMEM_DYN (3*STG_SZ)

__global__ void __launch_bounds__(256, 2)
gemm_bf16x3(const __nv_bfloat16* __restrict__ Ah, const __nv_bfloat16* __restrict__ Al,
            int AKD, size_t aZ,
            const __nv_bfloat16* __restrict__ Bh, const __nv_bfloat16* __restrict__ Bl, size_t bZ,
            const float* __restrict__ bias, size_t biasZ,
            __nv_bfloat16* __restrict__ oH, __nv_bfloat16* __restrict__ oL, size_t oZ, int ldo,
            int K, int relu, int p3)
{
    extern __shared__ char smem[];
    __shared__ float sbias[128];
    const int tid=threadIdx.x, wid=tid>>5, lane=tid&31;
    const size_t z=blockIdx.z;
    Ah+=z*aZ; Al+=z*aZ; Bh+=z*bZ; Bl+=z*bZ; oH+=z*oZ; oL+=z*oZ; bias+=z*biasZ;

    const int Nbase=blockIdx.x*128, Mbase=blockIdx.y*128;
    const int warpM=wid&1, warpN=wid>>1;
    if(tid<128) sbias[tid]=bias[Nbase+tid];
    const uint32_t sbase=smem_u32(smem);

    auto load_stage=[&](int s){
        const uint32_t sb = sbase + (uint32_t)(s%3)*STG_SZ;
        const int kb = s*32;
        #pragma unroll
        for(int i=0;i<2;++i){
            int idx=tid+i*256, r=idx>>2, c=idx&3;
            uint32_t dst = sb + (uint32_t)(r*64 + ((c ^ ((r>>1)&3))*16));
            size_t ga=(size_t)(Mbase+r)*AKD+kb+c*8, gb=(size_t)(Nbase+r)*AKD+kb+c*8;
            cpa16(dst,        Ah+ga);
            cpa16(dst+8192,   Al+ga);
            cpa16(dst+16384,  Bh+gb);
            if(p3) cpa16(dst+24576, Bl+gb);
        }
        CP_COMMIT();
    };

    float acc[4][4][4];
    #pragma unroll
    for(int m=0;m<4;++m)
        #pragma unroll
        for(int n=0;n<4;++n){acc[m][n][0]=0;acc[m][n][1]=0;acc[m][n][2]=0;acc[m][n][3]=0;}

    const int NS=K>>5;
    load_stage(0); load_stage(1);

    for(int s=0;s<NS;++s){
        if(s+1<NS) asm volatile("cp.async.wait_group 1;":::"memory");
        else       asm volatile("cp.async.wait_group 0;":::"memory");
        __syncthreads();
        if(s+2<NS) load_stage(s+2);
        const uint32_t sb = sbase + (uint32_t)(s%3)*STG_SZ;

        uint32_t bf[2][2][4][2];   // [ks][hi/lo][ntile][2]
        #pragma unroll
        for(int ks=0;ks<2;++ks){
            #pragma unroll
            for(int ntp=0;ntp<2;++ntp){
                int grp=lane>>3, tile=ntp*2+(grp>>1);
                int n=warpN*32+tile*8+(lane&7);
                int cc=(ks*2+(grp&1))^((n>>1)&3);
                uint32_t ad=sb+16384u+(uint32_t)(n*64+cc*16);
                uint32_t t[4];
                ldsm4(t, ad);
                bf[ks][0][2*ntp][0]=t[0]; bf[ks][0][2*ntp][1]=t[1];
                bf[ks][0][2*ntp+1][0]=t[2]; bf[ks][0][2*ntp+1][1]=t[3];
                if(p3){
                    ldsm4(t, ad + 8192);
                    bf[ks][1][2*ntp][0]=t[0]; bf[ks][1][2*ntp][1]=t[1];
                    bf[ks][1][2*ntp+1][0]=t[2]; bf[ks][1][2*ntp+1][1]=t[3];
                }
            }
        }

        auto ldA=[&](int idx, uint32_t* a0, uint32_t* a1){
            int ks=idx>>2, mt=idx&3;
            int r=warpM*64+mt*16+(lane&15);
            int cc=(ks*2+(lane>>4))^((r>>1)&3);
            uint32_t ad=sb+(uint32_t)(r*64+cc*16);
            ldsm4(a0, ad);
            ldsm4(a1, ad + 8192);
        };

        uint32_t Abuf[2][2][4];
        ldA(0, Abuf[0][0], Abuf[0][1]);
        #pragma unroll
        for(int idx=0; idx<8; ++idx){
            int ks=idx>>2, mt=idx&3;
            int cur=idx&1, nx=cur^1;
            if(idx<7) ldA(idx+1, Abuf[nx][0], Abuf[nx][1]);
            #pragma unroll
            for(int nt=0;nt<4;++nt) mma16816(acc[mt][nt], Abuf[cur][0], bf[ks][0][nt]); // hi*hi
            if(p3){
                #pragma unroll
                for(int nt=0;nt<4;++nt) mma16816(acc[mt][nt], Abuf[cur][0], bf[ks][1][nt]); // hi*lo
            }
            #pragma unroll
            for(int nt=0;nt<4;++nt) mma16816(acc[mt][nt], Abuf[cur][1], bf[ks][0][nt]); // lo*hi
        }
    }

    #pragma unroll
    for(int mt=0;mt<4;++mt){
        #pragma unroll
        for(int nt=0;nt<4;++nt){
            int rl=warpM*64+mt*16+(lane>>2);
            int cl=warpN*32+nt*8+(lane&3)*2;
            #pragma unroll
            for(int h=0;h<2;++h){
                int row=Mbase+rl+h*8;
                float v0=acc[mt][nt][2*h]  +sbias[cl];
                float v1=acc[mt][nt][2*h+1]+sbias[cl+1];
                if(relu){ v0=fmaxf(v0,0.f); v1=fmaxf(v1,0.f); }
                __nv_bfloat16 h0=__float2bfloat16(v0), h1=__float2bfloat16(v1);
                __nv_bfloat162 hv; hv.x=h0; hv.y=h1;
                __nv_bfloat162 lv; lv.x=__float2bfloat16(v0-__bfloat162float(h0));
                                   lv.y=__float2bfloat16(v1-__bfloat162float(h1));
                size_t o=(size_t)row*ldo+Nbase+cl;
                *reinterpret_cast<uint32_t*>(oH+o)=*reinterpret_cast<uint32_t*>(&hv);
                *reinterpret_cast<uint32_t*>(oL+o)=*reinterpret_cast<uint32_t*>(&lv);
            }
        }
    }
}

__global__ void transpose_split(const float* __restrict__ src, int KD, int ND, int KOUT,
                                __nv_bfloat16* __restrict__ dH, __nv_bfloat16* __restrict__ dL)
{
    __shared__ float t[32][33];
    const int mz=blockIdx.z;
    src+=(size_t)mz*KD*ND; dH+=(size_t)mz*ND*KOUT; dL+=(size_t)mz*ND*KOUT;
    const int kt=blockIdx.x*32, nt=blockIdx.y*32, tx=threadIdx.x, ty=threadIdx.y;
    for(int r=ty;r<32;r+=8){ int k=kt+r; t[r][tx]=(k<KD)?src[(size_t)k*ND+nt+tx]:0.f; }
    __syncthreads();
    for(int r=ty;r<32;r+=8){ int n=nt+r, k=kt+tx;
        float v=t[tx][r]; __nv_bfloat16 h=__float2bfloat16(v);
        dH[(size_t)n*KOUT+k]=h; dL[(size_t)n*KOUT+k]=__float2bfloat16(v-__bfloat162float(h)); }
}

__global__ void split_pad(const float* __restrict__ src,
                          __nv_bfloat16* __restrict__ dH, __nv_bfloat16* __restrict__ dL)
{
    size_t i=(size_t)blockIdx.x*256+threadIdx.x;
    if(i>=17ull*WI) return;
    size_t z=i/WI, rem=i%WI;
    int k=(int)(rem/HDIM), j=(int)(rem%HDIM);
    float v=(k<96)?src[(z*96+k)*HDIM+j]:0.f;
    __nv_bfloat16 h=__float2bfloat16(v);
    dH[i]=h; dL[i]=__float2bfloat16(v-__bfloat162float(h));
}

__global__ void bcomb_k(const float* __restrict__ bin_f, const float* __restrict__ bin_b,
                        const float* __restrict__ Wblk, const float* __restrict__ bblk,
                        float* __restrict__ bcomb)
{
    int n=blockIdx.x*256+threadIdx.x;
    int z=blockIdx.y;
    const float* bin=(z<17)?(bin_f+(size_t)z*HDIM):(bin_b+(size_t)(z-17)*HDIM);
    float acc=bblk[n];
    for(int j=0;j<HDIM;++j) acc+=bin[j]*Wblk[(size_t)j*HDIM+n];
    bcomb[(size_t)z*HDIM+n]=acc;
}

__global__ void init_prev_k(const float* __restrict__ x,
                            __nv_bfloat16* __restrict__ phi, __nv_bfloat16* __restrict__ plo)
{
    int i=blockIdx.x*256+threadIdx.x; if(i>=BATCH*KP) return;
    int b=i>>7, c=i&127;
    float v=(c<IN_DIM)?x[b*IN_DIM+c]:0.f;
    __nv_bfloat16 h=__float2bfloat16(v);
    __nv_bfloat16 l=__float2bfloat16(v-__bfloat162float(h));
    size_t o2=(size_t)BATCH*KP;
    phi[i]=h; plo[i]=l; phi[i+o2]=h; plo[i+o2]=l;
}

__global__ void out_proj(const __nv_bfloat16* __restrict__ hHi, const __nv_bfloat16* __restrict__ hLo,
                         const float* __restrict__ Wout, const float* __restrict__ bout,
                         float* __restrict__ tot,
                         __nv_bfloat16* __restrict__ ph, __nv_bfloat16* __restrict__ pl,
                         int level)
{
    const int b=blockIdx.x, tid=threadIdx.x;
    const size_t hoff=(size_t)b*HDIM;
    __shared__ float sh[HDIM];
    #pragma unroll
    for(int q=0;q<4;++q){ int k=tid+q*256;
        sh[k]=__bfloat162float(hHi[hoff+k])+__bfloat162float(hLo[hoff+k]); }
    __syncthreads();
    const int warp=tid>>5, lane=tid&31;
    if(warp<ODIM){
        float acc=0.f;
        for(int k=lane;k<HDIM;k+=32) acc+=sh[k]*Wout[k*ODIM+warp];
        #pragma unroll
        for(int off=16;off>0;off>>=1) acc+=__shfl_down_sync(0xffffffffu,acc,off);
        if(lane==0){
            float val=acc+bout[warp];
            tot[b*TOTW+level*ODIM+warp]=val;
            if(level<LEVELS-1){
                int pc=b*KP+IN_DIM+level*ODIM+warp;
                __nv_bfloat16 h=__float2bfloat16(val);
                ph[pc]=h; pl[pc]=__float2bfloat16(val-__bfloat162float(h));
            }
        }
    }
}

__global__ void attn_final(const float* __restrict__ totbuf,
                           const float* __restrict__ W1, const float* __restrict__ W2,
                           const float* __restrict__ W3, const float* __restrict__ W4,
                           const float* __restrict__ b4, float* __restrict__ out)
{
    const int b=blockIdx.x;
    const float* totF=totbuf; const float* totB=totbuf+(size_t)BATCH*TOTW;
    __shared__ float tf[ODIM][LEVELS], tb[ODIM][LEVELS];
    __shared__ float q[LEVELS][ODIM], kk[ODIM][LEVELS], v[LEVELS][ODIM];
    __shared__ float attn[LEVELS][LEVELS], res[TOTW], w1[25], w2[25], w3[25];
    const int tid=threadIdx.x;
    if(tid<TOTW){
        reinterpret_cast<float*>(tf)[tid]=totF[b*TOTW+tid];
        int d=tid/LEVELS, t=tid%LEVELS;
        tb[d][t]=totB[b*TOTW+d*LEVELS+(LEVELS-1-t)];
    }
    if(tid<25){ w1[tid]=W1[tid]; w2[tid]=W2[tid]; w3[tid]=W3[tid]; }
    __syncthreads();
    if(tid<TOTW){
        int t=tid/ODIM, e=tid%ODIM;
        float sq=0.f,sk=0.f,sv=0.f;
        #pragma unroll
        for(int d=0;d<ODIM;++d){
            sq+=tf[d][t]*w1[d*ODIM+e]; sk+=tb[d][t]*w2[d*ODIM+e]; sv+=tb[d][t]*w3[d*ODIM+e]; }
        q[t][e]=sq; kk[e][t]=sk; v[t][e]=sv;
    }
    __syncthreads();
    for(int idx=tid;idx<LEVELS*LEVELS;idx+=blockDim.x){
        int t=idx/LEVELS, s=idx%LEVELS;
        float sc=0.f;
        #pragma unroll
        for(int e=0;e<ODIM;++e) sc+=q[t][e]*kk[e][s];
        attn[t][s]=sc;
    }
    __syncthreads();
    if(tid<LEVELS){
        int s=tid; float mx=-1e30f;
        for(int t=0;t<LEVELS;++t) mx=fmaxf(mx,attn[t][s]);
        float sm=0.f;
        for(int t=0;t<LEVELS;++t){ float e=expf(attn[t][s]-mx); attn[t][s]=e; sm+=e; }
        float inv=1.f/sm;
        for(int t=0;t<LEVELS;++t) attn[t][s]*=inv;
    }
    __syncthreads();
    if(tid<TOTW){
        int t=tid/ODIM, e=tid%ODIM; float r=0.f;
        for(int s=0;s<LEVELS;++s) r+=attn[t][s]*v[s][e];
        res[tid]=r;
    }
    __syncthreads();
    if(tid<TOTW){
        int o=tid; float y=b4[o];
        for(int j=0;j<TOTW;++j) y+=res[j]*W4[j*TOTW+o];
        out[(size_t)b*TOTW+o]=y;
    }
}

extern "C" void kernel_launch(void* const* d_in, const int* in_sizes, int n_in,
                              void* d_out, int out_size)
{
    const float* x=(const float*)d_in[0];
    const float* Win_f=(const float*)d_in[1];  const float* bin_f=(const float*)d_in[2];
    const float* Win_b=(const float*)d_in[3];  const float* bin_b=(const float*)d_in[4];
    const float* Wblk=(const float*)d_in[5];   const float* bblk=(const float*)d_in[6];
    const float* Wout_f=(const float*)d_in[7]; const float* bout_f=(const float*)d_in[8];
    const float* Wout_b=(const float*)d_in[9]; const float* bout_b=(const float*)d_in[10];
    const float* W1=(const float*)d_in[11]; const float* W2=(const float*)d_in[12];
    const float* W3=(const float*)d_in[13]; const float* W4=(const float*)d_in[14];
    const float* b4=(const float*)d_in[15];
    float* out=(float*)d_out;

    __nv_bfloat16 *hhi,*hlo,*phi,*plo,*wphi,*wplo,*wchi,*wclo,*wbhi,*wblo;
    float *tot,*bcomb,*zero;
    cudaGetSymbolAddress((void**)&hhi,g_hhi);   cudaGetSymbolAddress((void**)&hlo,g_hlo);
    cudaGetSymbolAddress((void**)&phi,g_phi);   cudaGetSymbolAddress((void**)&plo,g_plo);
    cudaGetSymbolAddress((void**)&wphi,g_wphi); cudaGetSymbolAddress((void**)&wplo,g_wplo);
    cudaGetSymbolAddress((void**)&wchi,g_wchi); cudaGetSymbolAddress((void**)&wclo,g_wclo);
    cudaGetSymbolAddress((void**)&wbhi,g_wbhi); cudaGetSymbolAddress((void**)&wblo,g_wblo);
    cudaGetSymbolAddress((void**)&tot,g_tot);   cudaGetSymbolAddress((void**)&bcomb,g_bcomb);
    cudaGetSymbolAddress((void**)&zero,g_zero);

    cudaFuncSetAttribute(gemm_bf16x3, cudaFuncAttributeMaxDynamicSharedMemorySize, SMEM_DYN);

    cudaStream_t sB;
    cudaStreamCreateWithFlags(&sB, cudaStreamNonBlocking);
    cudaEvent_t eFork, eJoin;
    cudaEventCreateWithFlags(&eFork, cudaEventDisableTiming);
    cudaEventCreateWithFlags(&eJoin, cudaEventDisableTiming);

    transpose_split<<<dim3(HDIM/32,HDIM/32,HS),dim3(32,8)>>>(Wblk,HDIM,HDIM,HDIM,wbhi,wblo);
    split_pad<<<(int)((17ull*WI+255)/256),256>>>(Win_f, wphi,       wplo);
    split_pad<<<(int)((17ull*WI+255)/256),256>>>(Win_b, wphi+17*WI, wplo+17*WI);
    bcomb_k<<<dim3(HDIM/256,34),256>>>(bin_f,bin_b,Wblk,bblk,bcomb);
    init_prev_k<<<(BATCH*KP+255)/256,256>>>(x,phi,plo);

    cudaEventRecord(eFork, 0);
    cudaStreamWaitEvent(sB, eFork, 0);

    // WcombT = WblkT0 @ WinPad^T (full 3-pass for exact weights)
    gemm_bf16x3<<<dim3(1,HDIM/128,LEVELS),256,SMEM_DYN,0>>>(
        wbhi, wblo, HDIM, 0, wphi, wplo, WI, zero, 0,
        wchi, wclo, WI, KP, HDIM, 0, 1);
    gemm_bf16x3<<<dim3(1,HDIM/128,LEVELS),256,SMEM_DYN,sB>>>(
        wbhi, wblo, HDIM, 0, wphi+17*WI, wplo+17*WI, WI, zero, 0,
        wchi+17*WI, wclo+17*WI, WI, KP, HDIM, 0, 1);

    dim3 gg(HDIM/128, BATCH/128, 1);
    const size_t PK=(size_t)BATCH*KP;

    for(int i=0;i<LEVELS;++i){
        gemm_bf16x3<<<gg,256,SMEM_DYN,0>>>(phi,plo,KP,0,
            wchi+(size_t)i*WI, wclo+(size_t)i*WI, 0,
            bcomb+(size_t)i*HDIM, 0,
            hhi, hlo, 0, HDIM, KP, 1, 0);
        gemm_bf16x3<<<gg,256,SMEM_DYN,sB>>>(phi+PK,plo+PK,KP,0,
            wchi+(size_t)(17+i)*WI, wclo+(size_t)(17+i)*WI, 0,
            bcomb+(size_t)(17+i)*HDIM, 0,
            hhi+2ull*HN, hlo+2ull*HN, 0, HDIM, KP, 1, 0);
        int cur=0;
        for(int j=1;j<HS;++j){
            gemm_bf16x3<<<gg,256,SMEM_DYN,0>>>(
                hhi+(size_t)cur*HN, hlo+(size_t)cur*HN, HDIM, 0,
                wbhi+(size_t)j*WB, wblo+(size_t)j*WB, 0,
                bblk+(size_t)j*HDIM, 0,
                hhi+(size_t)(cur^1)*HN, hlo+(size_t)(cur^1)*HN, 0, HDIM, HDIM, 1, 0);
            gemm_bf16x3<<<gg,256,SMEM_DYN,sB>>>(
                hhi+(size_t)(2+cur)*HN, hlo+(size_t)(2+cur)*HN, HDIM, 0,
                wbhi+(size_t)j*WB, wblo+(size_t)j*WB, 0,
                bblk+(size_t)j*HDIM, 0,
                hhi+(size_t)(2+(cur^1))*HN, hlo+(size_t)(2+(cur^1))*HN, 0, HDIM, HDIM, 1, 0);
            cur^=1;
        }
        out_proj<<<dim3(BATCH,1,1),256,0,0>>>(hhi, hlo,
            Wout_f+(size_t)i*HDIM*ODIM, bout_f+i*ODIM, tot, phi, plo, i);
        out_proj<<<dim3(BATCH,1,1),256,0,sB>>>(hhi+2ull*HN, hlo+2ull*HN,
            Wout_b+(size_t)i*HDIM*ODIM, bout_b+i*ODIM, tot+(size_t)BATCH*TOTW, phi+PK, plo+PK, i);
    }

    cudaEventRecord(eJoin, sB);
    cudaStreamWaitEvent(0, eJoin, 0);
    attn_final<<<BATCH,128>>>(tot,W1,W2,W3,W4,b4,out);
}

// round 15
// speedup vs baseline: 1.4952x; 1.0563x over previous
#include <cuda_runtime.h>
#include <cuda_bf16.h>
#include <cstdint>

#define BATCH 4096
#define IN_DIM 16
#define LEVELS 17
#define ODIM 5
#define HDIM 1024
#define HS 3
#define KP 128
#define TOTW (ODIM*LEVELS)
#define HN (BATCH*HDIM)
#define WI ((size_t)KP*HDIM)
#define WB ((size_t)HDIM*HDIM)

__device__ __nv_bfloat16 g_hhi[4ull*HN], g_hlo[4ull*HN];
__device__ __nv_bfloat16 g_phi[2ull*BATCH*KP], g_plo[2ull*BATCH*KP];
__device__ __nv_bfloat16 g_wphi[34ull*WI], g_wplo[34ull*WI];
__device__ __nv_bfloat16 g_wchi[34ull*WI], g_wclo[34ull*WI];
__device__ __nv_bfloat16 g_wbhi[3ull*WB], g_wblo[3ull*WB];
__device__ float g_bcomb[34ull*HDIM];
__device__ float g_zero[128];
__device__ float g_tot[2ull*BATCH*TOTW];

__device__ __forceinline__ uint32_t smem_u32(const void* p){ return (uint32_t)__cvta_generic_to_shared(p); }
__device__ __forceinline__ void cpa16(uint32_t d, const void* s){
    asm volatile("cp.async.cg.shared.global [%0], [%1], 16;" :: "r"(d),"l"(s)); }
#define CP_COMMIT() asm volatile("cp.async.commit_group;" ::: "memory")
__device__ __forceinline__ void ldsm4(uint32_t* r, uint32_t a){
    asm volatile("ldmatrix.sync.aligned.m8n8.x4.shared.b16 {%0,%1,%2,%3}, [%4];"
        : "=r"(r[0]),"=r"(r[1]),"=r"(r[2]),"=r"(r[3]) : "r"(a));
}
__device__ __forceinline__ void mma16816(float* d, const uint32_t* a, const uint32_t* b){
    asm("mma.sync.aligned.m16n8k16.row.col.f32.bf16.bf16.f32 "
        "{%0,%1,%2,%3}, {%4,%5,%6,%7}, {%8,%9}, {%0,%1,%2,%3};"
        : "+f"(d[0]),"+f"(d[1]),"+f"(d[2]),"+f"(d[3])
        : "r"(a[0]),"r"(a[1]),"r"(a[2]),"r"(a[3]), "r"(b[0]),"r"(b[1]));
}

// GEMM: C = act(A @ B^T + bias).
// pm=3: hi*hi + hi*lo + lo*hi.  pm=2: hi*hi + lo*hi.  pm=1: hi*hi only (no A-lo/B-lo loads).
// wlo: store the lo half of the output (skip when consumer never reads it).
#define STG_SZ 32768
#define SMEM_DYN (3*STG_SZ)

__global__ void __launch_bounds__(256, 2)
gemm_bf16x3(const __nv_bfloat16* __restrict__ Ah, const __nv_bfloat16* __restrict__ Al,
            int AKD, size_t aZ,
            const __nv_bfloat16* __restrict__ Bh, const __nv_bfloat16* __restrict__ Bl, size_t bZ,
            const float* __restrict__ bias, size_t biasZ,
            __nv_bfloat16* __restrict__ oH, __nv_bfloat16* __restrict__ oL, size_t oZ, int ldo,
            int K, int relu, int pm, int wlo)
{
    extern __shared__ char smem[];
    __shared__ float sbias[128];
    const int tid=threadIdx.x, wid=tid>>5, lane=tid&31;
    const size_t z=blockIdx.z;
    Ah+=z*aZ; Al+=z*aZ; Bh+=z*bZ; Bl+=z*bZ; oH+=z*oZ; oL+=z*oZ; bias+=z*biasZ;

    const int Nbase=blockIdx.x*128, Mbase=blockIdx.y*128;
    const int warpM=wid&1, warpN=wid>>1;
    if(tid<128) sbias[tid]=bias[Nbase+tid];
    const uint32_t sbase=smem_u32(smem);

    auto load_stage=[&](int s){
        const uint32_t sb = sbase + (uint32_t)(s%3)*STG_SZ;
        const int kb = s*32;
        #pragma unroll
        for(int i=0;i<2;++i){
            int idx=tid+i*256, r=idx>>2, c=idx&3;
            uint32_t dst = sb + (uint32_t)(r*64 + ((c ^ ((r>>1)&3))*16));
            size_t ga=(size_t)(Mbase+r)*AKD+kb+c*8, gb=(size_t)(Nbase+r)*AKD+kb+c*8;
            cpa16(dst,        Ah+ga);
            if(pm>=2) cpa16(dst+8192,  Al+ga);
            cpa16(dst+16384,  Bh+gb);
            if(pm>=3) cpa16(dst+24576, Bl+gb);
        }
        CP_COMMIT();
    };

    float acc[4][4][4];
    #pragma unroll
    for(int m=0;m<4;++m)
        #pragma unroll
        for(int n=0;n<4;++n){acc[m][n][0]=0;acc[m][n][1]=0;acc[m][n][2]=0;acc[m][n][3]=0;}

    const int NS=K>>5;
    load_stage(0); load_stage(1);

    for(int s=0;s<NS;++s){
        if(s+1<NS) asm volatile("cp.async.wait_group 1;":::"memory");
        else       asm volatile("cp.async.wait_group 0;":::"memory");
        __syncthreads();
        if(s+2<NS) load_stage(s+2);
        const uint32_t sb = sbase + (uint32_t)(s%3)*STG_SZ;

        uint32_t bf[2][2][4][2];   // [ks][hi/lo][ntile][2]
        #pragma unroll
        for(int ks=0;ks<2;++ks){
            #pragma unroll
            for(int ntp=0;ntp<2;++ntp){
                int grp=lane>>3, tile=ntp*2+(grp>>1);
                int n=warpN*32+tile*8+(lane&7);
                int cc=(ks*2+(grp&1))^((n>>1)&3);
                uint32_t ad=sb+16384u+(uint32_t)(n*64+cc*16);
                uint32_t t[4];
                ldsm4(t, ad);
                bf[ks][0][2*ntp][0]=t[0]; bf[ks][0][2*ntp][1]=t[1];
                bf[ks][0][2*ntp+1][0]=t[2]; bf[ks][0][2*ntp+1][1]=t[3];
                if(pm>=3){
                    ldsm4(t, ad + 8192);
                    bf[ks][1][2*ntp][0]=t[0]; bf[ks][1][2*ntp][1]=t[1];
                    bf[ks][1][2*ntp+1][0]=t[2]; bf[ks][1][2*ntp+1][1]=t[3];
                }
            }
        }

        auto ldA=[&](int idx, uint32_t* a0, uint32_t* a1){
            int ks=idx>>2, mt=idx&3;
            int r=warpM*64+mt*16+(lane&15);
            int cc=(ks*2+(lane>>4))^((r>>1)&3);
            uint32_t ad=sb+(uint32_t)(r*64+cc*16);
            ldsm4(a0, ad);
            if(pm>=2) ldsm4(a1, ad + 8192);
        };

        uint32_t Abuf[2][2][4];
        ldA(0, Abuf[0][0], Abuf[0][1]);
        #pragma unroll
        for(int idx=0; idx<8; ++idx){
            int ks=idx>>2, mt=idx&3;
            int cur=idx&1, nx=cur^1;
            if(idx<7) ldA(idx+1, Abuf[nx][0], Abuf[nx][1]);
            #pragma unroll
            for(int nt=0;nt<4;++nt) mma16816(acc[mt][nt], Abuf[cur][0], bf[ks][0][nt]); // hi*hi
            if(pm>=3){
                #pragma unroll
                for(int nt=0;nt<4;++nt) mma16816(acc[mt][nt], Abuf[cur][0], bf[ks][1][nt]); // hi*lo
            }
            if(pm>=2){
                #pragma unroll
                for(int nt=0;nt<4;++nt) mma16816(acc[mt][nt], Abuf[cur][1], bf[ks][0][nt]); // lo*hi
            }
        }
    }

    #pragma unroll
    for(int mt=0;mt<4;++mt){
        #pragma unroll
        for(int nt=0;nt<4;++nt){
            int rl=warpM*64+mt*16+(lane>>2);
            int cl=warpN*32+nt*8+(lane&3)*2;
            #pragma unroll
            for(int h=0;h<2;++h){
                int row=Mbase+rl+h*8;
                float v0=acc[mt][nt][2*h]  +sbias[cl];
                float v1=acc[mt][nt][2*h+1]+sbias[cl+1];
                if(relu){ v0=fmaxf(v0,0.f); v1=fmaxf(v1,0.f); }
                __nv_bfloat16 h0=__float2bfloat16(v0), h1=__float2bfloat16(v1);
                __nv_bfloat162 hv; hv.x=h0; hv.y=h1;
                size_t o=(size_t)row*ldo+Nbase+cl;
                *reinterpret_cast<uint32_t*>(oH+o)=*reinterpret_cast<uint32_t*>(&hv);
                if(wlo){
                    __nv_bfloat162 lv; lv.x=__float2bfloat16(v0-__bfloat162float(h0));
                                       lv.y=__float2bfloat16(v1-__bfloat162float(h1));
                    *reinterpret_cast<uint32_t*>(oL+o)=*reinterpret_cast<uint32_t*>(&lv);
                }
            }
        }
    }
}

__global__ void transpose_split(const float* __restrict__ src, int KD, int ND, int KOUT,
                                __nv_bfloat16* __restrict__ dH, __nv_bfloat16* __restrict__ dL)
{
    __shared__ float t[32][33];
    const int mz=blockIdx.z;
    src+=(size_t)mz*KD*ND; dH+=(size_t)mz*ND*KOUT; dL+=(size_t)mz*ND*KOUT;
    const int kt=blockIdx.x*32, nt=blockIdx.y*32, tx=threadIdx.x, ty=threadIdx.y;
    for(int r=ty;r<32;r+=8){ int k=kt+r; t[r][tx]=(k<KD)?src[(size_t)k*ND+nt+tx]:0.f; }
    __syncthreads();
    for(int r=ty;r<32;r+=8){ int n=nt+r, k=kt+tx;
        float v=t[tx][r]; __nv_bfloat16 h=__float2bfloat16(v);
        dH[(size_t)n*KOUT+k]=h; dL[(size_t)n*KOUT+k]=__float2bfloat16(v-__bfloat162float(h)); }
}

__global__ void split_pad(const float* __restrict__ src,
                          __nv_bfloat16* __restrict__ dH, __nv_bfloat16* __restrict__ dL)
{
    size_t i=(size_t)blockIdx.x*256+threadIdx.x;
    if(i>=17ull*WI) return;
    size_t z=i/WI, rem=i%WI;
    int k=(int)(rem/HDIM), j=(int)(rem%HDIM);
    float v=(k<96)?src[(z*96+k)*HDIM+j]:0.f;
    __nv_bfloat16 h=__float2bfloat16(v);
    dH[i]=h; dL[i]=__float2bfloat16(v-__bfloat162float(h));
}

__global__ void bcomb_k(const float* __restrict__ bin_f, const float* __restrict__ bin_b,
                        const float* __restrict__ Wblk, const float* __restrict__ bblk,
                        float* __restrict__ bcomb)
{
    int n=blockIdx.x*256+threadIdx.x;
    int z=blockIdx.y;
    const float* bin=(z<17)?(bin_f+(size_t)z*HDIM):(bin_b+(size_t)(z-17)*HDIM);
    float acc=bblk[n];
    for(int j=0;j<HDIM;++j) acc+=bin[j]*Wblk[(size_t)j*HDIM+n];
    bcomb[(size_t)z*HDIM+n]=acc;
}

__global__ void init_prev_k(const float* __restrict__ x,
                            __nv_bfloat16* __restrict__ phi, __nv_bfloat16* __restrict__ plo)
{
    int i=blockIdx.x*256+threadIdx.x; if(i>=BATCH*KP) return;
    int b=i>>7, c=i&127;
    float v=(c<IN_DIM)?x[b*IN_DIM+c]:0.f;
    __nv_bfloat16 h=__float2bfloat16(v);
    __nv_bfloat16 l=__float2bfloat16(v-__bfloat162float(h));
    size_t o2=(size_t)BATCH*KP;
    phi[i]=h; plo[i]=l; phi[i+o2]=h; plo[i+o2]=l;
}

__global__ void out_proj(const __nv_bfloat16* __restrict__ hHi, const __nv_bfloat16* __restrict__ hLo,
                         const float* __restrict__ Wout, const float* __restrict__ bout,
                         float* __restrict__ tot,
                         __nv_bfloat16* __restrict__ ph, __nv_bfloat16* __restrict__ pl,
                         int level)
{
    const int b=blockIdx.x, tid=threadIdx.x;
    const size_t hoff=(size_t)b*HDIM;
    __shared__ float sh[HDIM];
    #pragma unroll
    for(int q=0;q<4;++q){ int k=tid+q*256;
        sh[k]=__bfloat162float(hHi[hoff+k])+__bfloat162float(hLo[hoff+k]); }
    __syncthreads();
    const int warp=tid>>5, lane=tid&31;
    if(warp<ODIM){
        float acc=0.f;
        for(int k=lane;k<HDIM;k+=32) acc+=sh[k]*Wout[k*ODIM+warp];
        #pragma unroll
        for(int off=16;off>0;off>>=1) acc+=__shfl_down_sync(0xffffffffu,acc,off);
        if(lane==0){
            float val=acc+bout[warp];
            tot[b*TOTW+level*ODIM+warp]=val;
            if(level<LEVELS-1){
                int pc=b*KP+IN_DIM+level*ODIM+warp;
                __nv_bfloat16 h=__float2bfloat16(val);
                ph[pc]=h; pl[pc]=__float2bfloat16(val-__bfloat162float(h));
            }
        }
    }
}

__global__ void attn_final(const float* __restrict__ totbuf,
                           const float* __restrict__ W1, const float* __restrict__ W2,
                           const float* __restrict__ W3, const float* __restrict__ W4,
                           const float* __restrict__ b4, float* __restrict__ out)
{
    const int b=blockIdx.x;
    const float* totF=totbuf; const float* totB=totbuf+(size_t)BATCH*TOTW;
    __shared__ float tf[ODIM][LEVELS], tb[ODIM][LEVELS];
    __shared__ float q[LEVELS][ODIM], kk[ODIM][LEVELS], v[LEVELS][ODIM];
    __shared__ float attn[LEVELS][LEVELS], res[TOTW], w1[25], w2[25], w3[25];
    const int tid=threadIdx.x;
    if(tid<TOTW){
        reinterpret_cast<float*>(tf)[tid]=totF[b*TOTW+tid];
        int d=tid/LEVELS, t=tid%LEVELS;
        tb[d][t]=totB[b*TOTW+d*LEVELS+(LEVELS-1-t)];
    }
    if(tid<25){ w1[tid]=W1[tid]; w2[tid]=W2[tid]; w3[tid]=W3[tid]; }
    __syncthreads();
    if(tid<TOTW){
        int t=tid/ODIM, e=tid%ODIM;
        float sq=0.f,sk=0.f,sv=0.f;
        #pragma unroll
        for(int d=0;d<ODIM;++d){
            sq+=tf[d][t]*w1[d*ODIM+e]; sk+=tb[d][t]*w2[d*ODIM+e]; sv+=tb[d][t]*w3[d*ODIM+e]; }
        q[t][e]=sq; kk[e][t]=sk; v[t][e]=sv;
    }
    __syncthreads();
    for(int idx=tid;idx<LEVELS*LEVELS;idx+=blockDim.x){
        int t=idx/LEVELS, s=idx%LEVELS;
        float sc=0.f;
        #pragma unroll
        for(int e=0;e<ODIM;++e) sc+=q[t][e]*kk[e][s];
        attn[t][s]=sc;
    }
    __syncthreads();
    if(tid<LEVELS){
        int s=tid; float mx=-1e30f;
        for(int t=0;t<LEVELS;++t) mx=fmaxf(mx,attn[t][s]);
        float sm=0.f;
        for(int t=0;t<LEVELS;++t){ float e=expf(attn[t][s]-mx); attn[t][s]=e; sm+=e; }
        float inv=1.f/sm;
        for(int t=0;t<LEVELS;++t) attn[t][s]*=inv;
    }
    __syncthreads();
    if(tid<TOTW){
        int t=tid/ODIM, e=tid%ODIM; float r=0.f;
        for(int s=0;s<LEVELS;++s) r+=attn[t][s]*v[s][e];
        res[tid]=r;
    }
    __syncthreads();
    if(tid<TOTW){
        int o=tid; float y=b4[o];
        for(int j=0;j<TOTW;++j) y+=res[j]*W4[j*TOTW+o];
        out[(size_t)b*TOTW+o]=y;
    }
}

extern "C" void kernel_launch(void* const* d_in, const int* in_sizes, int n_in,
                              void* d_out, int out_size)
{
    const float* x=(const float*)d_in[0];
    const float* Win_f=(const float*)d_in[1];  const float* bin_f=(const float*)d_in[2];
    const float* Win_b=(const float*)d_in[3];  const float* bin_b=(const float*)d_in[4];
    const float* Wblk=(const float*)d_in[5];   const float* bblk=(const float*)d_in[6];
    const float* Wout_f=(const float*)d_in[7]; const float* bout_f=(const float*)d_in[8];
    const float* Wout_b=(const float*)d_in[9]; const float* bout_b=(const float*)d_in[10];
    const float* W1=(const float*)d_in[11]; const float* W2=(const float*)d_in[12];
    const float* W3=(const float*)d_in[13]; const float* W4=(const float*)d_in[14];
    const float* b4=(const float*)d_in[15];
    float* out=(float*)d_out;

    __nv_bfloat16 *hhi,*hlo,*phi,*plo,*wphi,*wplo,*wchi,*wclo,*wbhi,*wblo;
    float *tot,*bcomb,*zero;
    cudaGetSymbolAddress((void**)&hhi,g_hhi);   cudaGetSymbolAddress((void**)&hlo,g_hlo);
    cudaGetSymbolAddress((void**)&phi,g_phi);   cudaGetSymbolAddress((void**)&plo,g_plo);
    cudaGetSymbolAddress((void**)&wphi,g_wphi); cudaGetSymbolAddress((void**)&wplo,g_wplo);
    cudaGetSymbolAddress((void**)&wchi,g_wchi); cudaGetSymbolAddress((void**)&wclo,g_wclo);
    cudaGetSymbolAddress((void**)&wbhi,g_wbhi); cudaGetSymbolAddress((void**)&wblo,g_wblo);
    cudaGetSymbolAddress((void**)&tot,g_tot);   cudaGetSymbolAddress((void**)&bcomb,g_bcomb);
    cudaGetSymbolAddress((void**)&zero,g_zero);

    cudaFuncSetAttribute(gemm_bf16x3, cudaFuncAttributeMaxDynamicSharedMemorySize, SMEM_DYN);

    cudaStream_t sB;
    cudaStreamCreateWithFlags(&sB, cudaStreamNonBlocking);
    cudaEvent_t eFork, eJoin;
    cudaEventCreateWithFlags(&eFork, cudaEventDisableTiming);
    cudaEventCreateWithFlags(&eJoin, cudaEventDisableTiming);

    transpose_split<<<dim3(HDIM/32,HDIM/32,HS),dim3(32,8)>>>(Wblk,HDIM,HDIM,HDIM,wbhi,wblo);
    split_pad<<<(int)((17ull*WI+255)/256),256>>>(Win_f, wphi,       wplo);
    split_pad<<<(int)((17ull*WI+255)/256),256>>>(Win_b, wphi+17*WI, wplo+17*WI);
    bcomb_k<<<dim3(HDIM/256,34),256>>>(bin_f,bin_b,Wblk,bblk,bcomb);
    init_prev_k<<<(BATCH*KP+255)/256,256>>>(x,phi,plo);

    cudaEventRecord(eFork, 0);
    cudaStreamWaitEvent(sB, eFork, 0);

    // WcombT = WblkT0 @ WinPad^T (full 3-pass for exact weights)
    gemm_bf16x3<<<dim3(1,HDIM/128,LEVELS),256,SMEM_DYN,0>>>(
        wbhi, wblo, HDIM, 0, wphi, wplo, WI, zero, 0,
        wchi, wclo, WI, KP, HDIM, 0, 3, 1);
    gemm_bf16x3<<<dim3(1,HDIM/128,LEVELS),256,SMEM_DYN,sB>>>(
        wbhi, wblo, HDIM, 0, wphi+17*WI, wplo+17*WI, WI, zero, 0,
        wchi+17*WI, wclo+17*WI, WI, KP, HDIM, 0, 3, 1);

    dim3 gg(HDIM/128, BATCH/128, 1);
    const size_t PK=(size_t)BATCH*KP;

    for(int i=0;i<LEVELS;++i){
        // fused entry: pm=2 (A-lo used), output lo never read (next gemm pm=1) -> wlo=0
        gemm_bf16x3<<<gg,256,SMEM_DYN,0>>>(phi,plo,KP,0,
            wchi+(size_t)i*WI, wclo+(size_t)i*WI, 0,
            bcomb+(size_t)i*HDIM, 0,
            hhi, hlo, 0, HDIM, KP, 1, 2, 0);
        gemm_bf16x3<<<gg,256,SMEM_DYN,sB>>>(phi+PK,plo+PK,KP,0,
            wchi+(size_t)(17+i)*WI, wclo+(size_t)(17+i)*WI, 0,
            bcomb+(size_t)(17+i)*HDIM, 0,
            hhi+2ull*HN, hlo+2ull*HN, 0, HDIM, KP, 1, 2, 0);
        int cur=0;
        for(int j=1;j<HS;++j){
            int wl = (j==HS-1) ? 1 : 0;   // only the last block output's lo is read (out_proj)
            gemm_bf16x3<<<gg,256,SMEM_DYN,0>>>(
                hhi+(size_t)cur*HN, hlo+(size_t)cur*HN, HDIM, 0,
                wbhi+(size_t)j*WB, wblo+(size_t)j*WB, 0,
                bblk+(size_t)j*HDIM, 0,
                hhi+(size_t)(cur^1)*HN, hlo+(size_t)(cur^1)*HN, 0, HDIM, HDIM, 1, 1, wl);
            gemm_bf16x3<<<gg,256,SMEM_DYN,sB>>>(
                hhi+(size_t)(2+cur)*HN, hlo+(size_t)(2+cur)*HN, HDIM, 0,
                wbhi+(size_t)j*WB, wblo+(size_t)j*WB, 0,
                bblk+(size_t)j*HDIM, 0,
                hhi+(size_t)(2+(cur^1))*HN, hlo+(size_t)(2+(cur^1))*HN, 0, HDIM, HDIM, 1, 1, wl);
            cur^=1;
        }
        out_proj<<<dim3(BATCH,1,1),256,0,0>>>(hhi, hlo,
            Wout_f+(size_t)i*HDIM*ODIM, bout_f+i*ODIM, tot, phi, plo, i);
        out_proj<<<dim3(BATCH,1,1),256,0,sB>>>(hhi+2ull*HN, hlo+2ull*HN,
            Wout_b+(size_t)i*HDIM*ODIM, bout_b+i*ODIM, tot+(size_t)BATCH*TOTW, phi+PK, plo+PK, i);
    }

    cudaEventRecord(eJoin, sB);
    cudaStreamWaitEvent(0, eJoin, 0);
    attn_final<<<BATCH,128>>>(tot,W1,W2,W3,W4,b4,out);
}

// round 16
// speedup vs baseline: 1.5904x; 1.0637x over previous
#include <cuda_runtime.h>
#include <cuda_bf16.h>
#include <cstdint>

#define BATCH 4096
#define IN_DIM 16
#define LEVELS 17
#define ODIM 5
#define HDIM 1024
#define HS 3
#define KP 128
#define TOTW (ODIM*LEVELS)
#define HN (BATCH*HDIM)
#define WI ((size_t)KP*HDIM)
#define WB ((size_t)HDIM*HDIM)

__device__ __nv_bfloat16 g_hhi[4ull*HN], g_hlo[4ull*HN];
__device__ __nv_bfloat16 g_phi[2ull*BATCH*KP], g_plo[2ull*BATCH*KP];
__device__ __nv_bfloat16 g_wphi[34ull*WI], g_wplo[34ull*WI];
__device__ __nv_bfloat16 g_wchi[34ull*WI], g_wclo[34ull*WI];
__device__ __nv_bfloat16 g_wbhi[3ull*WB], g_wblo[3ull*WB];
__device__ float g_bcomb[34ull*HDIM];
__device__ float g_zero[128];
__device__ float g_tot[2ull*BATCH*TOTW];

__device__ __forceinline__ uint32_t smem_u32(const void* p){ return (uint32_t)__cvta_generic_to_shared(p); }
__device__ __forceinline__ void cpa16(uint32_t d, const void* s){
    asm volatile("cp.async.cg.shared.global [%0], [%1], 16;" :: "r"(d),"l"(s)); }
#define CP_COMMIT() asm volatile("cp.async.commit_group;" ::: "memory")
__device__ __forceinline__ void ldsm4(uint32_t* r, uint32_t a){
    asm volatile("ldmatrix.sync.aligned.m8n8.x4.shared.b16 {%0,%1,%2,%3}, [%4];"
        : "=r"(r[0]),"=r"(r[1]),"=r"(r[2]),"=r"(r[3]) : "r"(a));
}
__device__ __forceinline__ void mma16816(float* d, const uint32_t* a, const uint32_t* b){
    asm("mma.sync.aligned.m16n8k16.row.col.f32.bf16.bf16.f32 "
        "{%0,%1,%2,%3}, {%4,%5,%6,%7}, {%8,%9}, {%0,%1,%2,%3};"
        : "+f"(d[0]),"+f"(d[1]),"+f"(d[2]),"+f"(d[3])
        : "r"(a[0]),"r"(a[1]),"r"(a[2]),"r"(a[3]), "r"(b[0]),"r"(b[1]));
}

// GEMM, BK=64 stages. pm=3: hh+hl+lh; pm=2: hh+lh; pm=1: hh only.
// Stage smem layout: Ahi 16K | Bhi 16K | [Alo 16K if pm>=2] | [Blo 16K if pm>=3]
// ring = min(3, K/64); host passes smem = ring*stg.
__global__ void __launch_bounds__(256, 2)
gemm_bf16x3(const __nv_bfloat16* __restrict__ Ah, const __nv_bfloat16* __restrict__ Al,
            int AKD, size_t aZ,
            const __nv_bfloat16* __restrict__ Bh, const __nv_bfloat16* __restrict__ Bl, size_t bZ,
            const float* __restrict__ bias, size_t biasZ,
            __nv_bfloat16* __restrict__ oH, __nv_bfloat16* __restrict__ oL, size_t oZ, int ldo,
            int K, int relu, int pm, int wlo)
{
    extern __shared__ char smem[];
    __shared__ float sbias[128];
    const int tid=threadIdx.x, wid=tid>>5, lane=tid&31;
    const size_t z=blockIdx.z;
    Ah+=z*aZ; Al+=z*aZ; Bh+=z*bZ; Bl+=z*bZ; oH+=z*oZ; oL+=z*oZ; bias+=z*biasZ;

    const int Nbase=blockIdx.x*128, Mbase=blockIdx.y*128;
    const int warpM=wid&1, warpN=wid>>1;
    if(tid<128) sbias[tid]=bias[Nbase+tid];
    const uint32_t sbase=smem_u32(smem);

    const uint32_t stg = 32768u + (pm>=2 ? 16384u:0u) + (pm>=3 ? 16384u:0u);
    const int NS = K>>6;
    const int ring = NS < 3 ? 2 : 3;
    const uint32_t offAlo = 32768u;
    const uint32_t offBlo = 32768u + (pm>=2 ? 16384u:0u);

    auto load_stage=[&](int s){
        const uint32_t sb = sbase + (uint32_t)(s%ring)*stg;
        const int kb = s*64;
        #pragma unroll
        for(int i=0;i<4;++i){
            int idx=tid+i*256, r=idx>>3, c=idx&7;
            uint32_t off = (uint32_t)(r*128 + ((c ^ (r&7))*16));
            size_t ga=(size_t)(Mbase+r)*AKD+kb+c*8, gb=(size_t)(Nbase+r)*AKD+kb+c*8;
            cpa16(sb+off,          Ah+ga);
            cpa16(sb+16384+off,    Bh+gb);
            if(pm>=2) cpa16(sb+offAlo+off, Al+ga);
            if(pm>=3) cpa16(sb+offBlo+off, Bl+gb);
        }
        CP_COMMIT();
    };

    float acc[4][4][4];
    #pragma unroll
    for(int m=0;m<4;++m)
        #pragma unroll
        for(int n=0;n<4;++n){acc[m][n][0]=0;acc[m][n][1]=0;acc[m][n][2]=0;acc[m][n][3]=0;}

    load_stage(0); if(NS>1) load_stage(1);

    for(int s=0;s<NS;++s){
        if(s+1<NS) asm volatile("cp.async.wait_group 1;":::"memory");
        else       asm volatile("cp.async.wait_group 0;":::"memory");
        __syncthreads();
        if(s+2<NS) load_stage(s+2);
        const uint32_t sb = sbase + (uint32_t)(s%ring)*stg;

        #pragma unroll
        for(int ks=0;ks<4;++ks){
            // B frags for this k16 slice
            uint32_t bh[4][2], bl[4][2];
            #pragma unroll
            for(int ntp=0;ntp<2;++ntp){
                int grp=lane>>3, tile=ntp*2+(grp>>1);
                int n=warpN*32+tile*8+(lane&7);
                int cc=(2*ks+(grp&1)) ^ (n&7);
                uint32_t ad = sb+16384u+(uint32_t)(n*128+cc*16);
                uint32_t t[4];
                ldsm4(t, ad);
                bh[2*ntp][0]=t[0]; bh[2*ntp][1]=t[1];
                bh[2*ntp+1][0]=t[2]; bh[2*ntp+1][1]=t[3];
                if(pm>=3){
                    ldsm4(t, sb+offBlo+(uint32_t)(n*128+cc*16));
                    bl[2*ntp][0]=t[0]; bl[2*ntp][1]=t[1];
                    bl[2*ntp+1][0]=t[2]; bl[2*ntp+1][1]=t[3];
                }
            }
            #pragma unroll
            for(int mt=0;mt<4;++mt){
                int r=warpM*64+mt*16+(lane&15);
                int cc=(2*ks+(lane>>4)) ^ (r&7);
                uint32_t a0[4], a1[4];
                ldsm4(a0, sb+(uint32_t)(r*128+cc*16));
                if(pm>=2) ldsm4(a1, sb+offAlo+(uint32_t)(r*128+cc*16));
                #pragma unroll
                for(int nt=0;nt<4;++nt) mma16816(acc[mt][nt], a0, bh[nt]);       // hi*hi
                if(pm>=3){
                    #pragma unroll
                    for(int nt=0;nt<4;++nt) mma16816(acc[mt][nt], a0, bl[nt]);   // hi*lo
                }
                if(pm>=2){
                    #pragma unroll
                    for(int nt=0;nt<4;++nt) mma16816(acc[mt][nt], a1, bh[nt]);   // lo*hi
                }
            }
        }
    }

    #pragma unroll
    for(int mt=0;mt<4;++mt){
        #pragma unroll
        for(int nt=0;nt<4;++nt){
            int rl=warpM*64+mt*16+(lane>>2);
            int cl=warpN*32+nt*8+(lane&3)*2;
            #pragma unroll
            for(int h=0;h<2;++h){
                int row=Mbase+rl+h*8;
                float v0=acc[mt][nt][2*h]  +sbias[cl];
                float v1=acc[mt][nt][2*h+1]+sbias[cl+1];
                if(relu){ v0=fmaxf(v0,0.f); v1=fmaxf(v1,0.f); }
                __nv_bfloat16 h0=__float2bfloat16(v0), h1=__float2bfloat16(v1);
                __nv_bfloat162 hv; hv.x=h0; hv.y=h1;
                size_t o=(size_t)row*ldo+Nbase+cl;
                *reinterpret_cast<uint32_t*>(oH+o)=*reinterpret_cast<uint32_t*>(&hv);
                if(wlo){
                    __nv_bfloat162 lv; lv.x=__float2bfloat16(v0-__bfloat162float(h0));
                                       lv.y=__float2bfloat16(v1-__bfloat162float(h1));
                    *reinterpret_cast<uint32_t*>(oL+o)=*reinterpret_cast<uint32_t*>(&lv);
                }
            }
        }
    }
}

__global__ void transpose_split(const float* __restrict__ src, int KD, int ND, int KOUT,
                                __nv_bfloat16* __restrict__ dH, __nv_bfloat16* __restrict__ dL)
{
    __shared__ float t[32][33];
    const int mz=blockIdx.z;
    src+=(size_t)mz*KD*ND; dH+=(size_t)mz*ND*KOUT; dL+=(size_t)mz*ND*KOUT;
    const int kt=blockIdx.x*32, nt=blockIdx.y*32, tx=threadIdx.x, ty=threadIdx.y;
    for(int r=ty;r<32;r+=8){ int k=kt+r; t[r][tx]=(k<KD)?src[(size_t)k*ND+nt+tx]:0.f; }
    __syncthreads();
    for(int r=ty;r<32;r+=8){ int n=nt+r, k=kt+tx;
        float v=t[tx][r]; __nv_bfloat16 h=__float2bfloat16(v);
        dH[(size_t)n*KOUT+k]=h; dL[(size_t)n*KOUT+k]=__float2bfloat16(v-__bfloat162float(h)); }
}

__global__ void split_pad(const float* __restrict__ src,
                          __nv_bfloat16* __restrict__ dH, __nv_bfloat16* __restrict__ dL)
{
    size_t i=(size_t)blockIdx.x*256+threadIdx.x;
    if(i>=17ull*WI) return;
    size_t z=i/WI, rem=i%WI;
    int k=(int)(rem/HDIM), j=(int)(rem%HDIM);
    float v=(k<96)?src[(z*96+k)*HDIM+j]:0.f;
    __nv_bfloat16 h=__float2bfloat16(v);
    dH[i]=h; dL[i]=__float2bfloat16(v-__bfloat162float(h));
}

__global__ void bcomb_k(const float* __restrict__ bin_f, const float* __restrict__ bin_b,
                        const float* __restrict__ Wblk, const float* __restrict__ bblk,
                        float* __restrict__ bcomb)
{
    int n=blockIdx.x*256+threadIdx.x;
    int z=blockIdx.y;
    const float* bin=(z<17)?(bin_f+(size_t)z*HDIM):(bin_b+(size_t)(z-17)*HDIM);
    float acc=bblk[n];
    for(int j=0;j<HDIM;++j) acc+=bin[j]*Wblk[(size_t)j*HDIM+n];
    bcomb[(size_t)z*HDIM+n]=acc;
}

__global__ void init_prev_k(const float* __restrict__ x,
                            __nv_bfloat16* __restrict__ phi, __nv_bfloat16* __restrict__ plo)
{
    int i=blockIdx.x*256+threadIdx.x; if(i>=BATCH*KP) return;
    int b=i>>7, c=i&127;
    float v=(c<IN_DIM)?x[b*IN_DIM+c]:0.f;
    __nv_bfloat16 h=__float2bfloat16(v);
    __nv_bfloat16 l=__float2bfloat16(v-__bfloat162float(h));
    size_t o2=(size_t)BATCH*KP;
    phi[i]=h; plo[i]=l; phi[i+o2]=h; plo[i+o2]=l;
}

__global__ void out_proj(const __nv_bfloat16* __restrict__ hHi, const __nv_bfloat16* __restrict__ hLo,
                         const float* __restrict__ Wout, const float* __restrict__ bout,
                         float* __restrict__ tot,
                         __nv_bfloat16* __restrict__ ph, __nv_bfloat16* __restrict__ pl,
                         int level)
{
    const int b=blockIdx.x, tid=threadIdx.x;
    const size_t hoff=(size_t)b*HDIM;
    __shared__ float sh[HDIM];
    #pragma unroll
    for(int q=0;q<4;++q){ int k=tid+q*256;
        sh[k]=__bfloat162float(hHi[hoff+k])+__bfloat162float(hLo[hoff+k]); }
    __syncthreads();
    const int warp=tid>>5, lane=tid&31;
    if(warp<ODIM){
        float acc=0.f;
        for(int k=lane;k<HDIM;k+=32) acc+=sh[k]*Wout[k*ODIM+warp];
        #pragma unroll
        for(int off=16;off>0;off>>=1) acc+=__shfl_down_sync(0xffffffffu,acc,off);
        if(lane==0){
            float val=acc+bout[warp];
            tot[b*TOTW+level*ODIM+warp]=val;
            if(level<LEVELS-1){
                int pc=b*KP+IN_DIM+level*ODIM+warp;
                __nv_bfloat16 h=__float2bfloat16(val);
                ph[pc]=h; pl[pc]=__float2bfloat16(val-__bfloat162float(h));
            }
        }
    }
}

__global__ void attn_final(const float* __restrict__ totbuf,
                           const float* __restrict__ W1, const float* __restrict__ W2,
                           const float* __restrict__ W3, const float* __restrict__ W4,
                           const float* __restrict__ b4, float* __restrict__ out)
{
    const int b=blockIdx.x;
    const float* totF=totbuf; const float* totB=totbuf+(size_t)BATCH*TOTW;
    __shared__ float tf[ODIM][LEVELS], tb[ODIM][LEVELS];
    __shared__ float q[LEVELS][ODIM], kk[ODIM][LEVELS], v[LEVELS][ODIM];
    __shared__ float attn[LEVELS][LEVELS], res[TOTW], w1[25], w2[25], w3[25];
    const int tid=threadIdx.x;
    if(tid<TOTW){
        reinterpret_cast<float*>(tf)[tid]=totF[b*TOTW+tid];
        int d=tid/LEVELS, t=tid%LEVELS;
        tb[d][t]=totB[b*TOTW+d*LEVELS+(LEVELS-1-t)];
    }
    if(tid<25){ w1[tid]=W1[tid]; w2[tid]=W2[tid]; w3[tid]=W3[tid]; }
    __syncthreads();
    if(tid<TOTW){
        int t=tid/ODIM, e=tid%ODIM;
        float sq=0.f,sk=0.f,sv=0.f;
        #pragma unroll
        for(int d=0;d<ODIM;++d){
            sq+=tf[d][t]*w1[d*ODIM+e]; sk+=tb[d][t]*w2[d*ODIM+e]; sv+=tb[d][t]*w3[d*ODIM+e]; }
        q[t][e]=sq; kk[e][t]=sk; v[t][e]=sv;
    }
    __syncthreads();
    for(int idx=tid;idx<LEVELS*LEVELS;idx+=blockDim.x){
        int t=idx/LEVELS, s=idx%LEVELS;
        float sc=0.f;
        #pragma unroll
        for(int e=0;e<ODIM;++e) sc+=q[t][e]*kk[e][s];
        attn[t][s]=sc;
    }
    __syncthreads();
    if(tid<LEVELS){
        int s=tid; float mx=-1e30f;
        for(int t=0;t<LEVELS;++t) mx=fmaxf(mx,attn[t][s]);
        float sm=0.f;
        for(int t=0;t<LEVELS;++t){ float e=expf(attn[t][s]-mx); attn[t][s]=e; sm+=e; }
        float inv=1.f/sm;
        for(int t=0;t<LEVELS;++t) attn[t][s]*=inv;
    }
    __syncthreads();
    if(tid<TOTW){
        int t=tid/ODIM, e=tid%ODIM; float r=0.f;
        for(int s=0;s<LEVELS;++s) r+=attn[t][s]*v[s][e];
        res[tid]=r;
    }
    __syncthreads();
    if(tid<TOTW){
        int o=tid; float y=b4[o];
        for(int j=0;j<TOTW;++j) y+=res[j]*W4[j*TOTW+o];
        out[(size_t)b*TOTW+o]=y;
    }
}

extern "C" void kernel_launch(void* const* d_in, const int* in_sizes, int n_in,
                              void* d_out, int out_size)
{
    const float* x=(const float*)d_in[0];
    const float* Win_f=(const float*)d_in[1];  const float* bin_f=(const float*)d_in[2];
    const float* Win_b=(const float*)d_in[3];  const float* bin_b=(const float*)d_in[4];
    const float* Wblk=(const float*)d_in[5];   const float* bblk=(const float*)d_in[6];
    const float* Wout_f=(const float*)d_in[7]; const float* bout_f=(const float*)d_in[8];
    const float* Wout_b=(const float*)d_in[9]; const float* bout_b=(const float*)d_in[10];
    const float* W1=(const float*)d_in[11]; const float* W2=(const float*)d_in[12];
    const float* W3=(const float*)d_in[13]; const float* W4=(const float*)d_in[14];
    const float* b4=(const float*)d_in[15];
    float* out=(float*)d_out;

    __nv_bfloat16 *hhi,*hlo,*phi,*plo,*wphi,*wplo,*wchi,*wclo,*wbhi,*wblo;
    float *tot,*bcomb,*zero;
    cudaGetSymbolAddress((void**)&hhi,g_hhi);   cudaGetSymbolAddress((void**)&hlo,g_hlo);
    cudaGetSymbolAddress((void**)&phi,g_phi);   cudaGetSymbolAddress((void**)&plo,g_plo);
    cudaGetSymbolAddress((void**)&wphi,g_wphi); cudaGetSymbolAddress((void**)&wplo,g_wplo);
    cudaGetSymbolAddress((void**)&wchi,g_wchi); cudaGetSymbolAddress((void**)&wclo,g_wclo);
    cudaGetSymbolAddress((void**)&wbhi,g_wbhi); cudaGetSymbolAddress((void**)&wblo,g_wblo);
    cudaGetSymbolAddress((void**)&tot,g_tot);   cudaGetSymbolAddress((void**)&bcomb,g_bcomb);
    cudaGetSymbolAddress((void**)&zero,g_zero);

    cudaFuncSetAttribute(gemm_bf16x3, cudaFuncAttributeMaxDynamicSharedMemorySize, 196608);

    cudaStream_t sB;
    cudaStreamCreateWithFlags(&sB, cudaStreamNonBlocking);
    cudaEvent_t eFork, eJoin;
    cudaEventCreateWithFlags(&eFork, cudaEventDisableTiming);
    cudaEventCreateWithFlags(&eJoin, cudaEventDisableTiming);

    transpose_split<<<dim3(HDIM/32,HDIM/32,HS),dim3(32,8)>>>(Wblk,HDIM,HDIM,HDIM,wbhi,wblo);
    split_pad<<<(int)((17ull*WI+255)/256),256>>>(Win_f, wphi,       wplo);
    split_pad<<<(int)((17ull*WI+255)/256),256>>>(Win_b, wphi+17*WI, wplo+17*WI);
    bcomb_k<<<dim3(HDIM/256,34),256>>>(bin_f,bin_b,Wblk,bblk,bcomb);
    init_prev_k<<<(BATCH*KP+255)/256,256>>>(x,phi,plo);

    cudaEventRecord(eFork, 0);
    cudaStreamWaitEvent(sB, eFork, 0);

    const int SM_P1 = 3*32768;   // pm=1 block gemms, ring 3
    const int SM_P2 = 2*49152;   // pm=2 fused (K=128 -> NS=2 -> ring 2)
    const int SM_P3 = 3*65536;   // pm=3 precompute, ring 3

    // WcombT = WblkT0 @ WinPad^T (full 3-pass for exact weights)
    gemm_bf16x3<<<dim3(1,HDIM/128,LEVELS),256,SM_P3,0>>>(
        wbhi, wblo, HDIM, 0, wphi, wplo, WI, zero, 0,
        wchi, wclo, WI, KP, HDIM, 0, 3, 1);
    gemm_bf16x3<<<dim3(1,HDIM/128,LEVELS),256,SM_P3,sB>>>(
        wbhi, wblo, HDIM, 0, wphi+17*WI, wplo+17*WI, WI, zero, 0,
        wchi+17*WI, wclo+17*WI, WI, KP, HDIM, 0, 3, 1);

    dim3 gg(HDIM/128, BATCH/128, 1);
    const size_t PK=(size_t)BATCH*KP;

    for(int i=0;i<LEVELS;++i){
        gemm_bf16x3<<<gg,256,SM_P2,0>>>(phi,plo,KP,0,
            wchi+(size_t)i*WI, wclo+(size_t)i*WI, 0,
            bcomb+(size_t)i*HDIM, 0,
            hhi, hlo, 0, HDIM, KP, 1, 2, 0);
        gemm_bf16x3<<<gg,256,SM_P2,sB>>>(phi+PK,plo+PK,KP,0,
            wchi+(size_t)(17+i)*WI, wclo+(size_t)(17+i)*WI, 0,
            bcomb+(size_t)(17+i)*HDIM, 0,
            hhi+2ull*HN, hlo+2ull*HN, 0, HDIM, KP, 1, 2, 0);
        int cur=0;
        for(int j=1;j<HS;++j){
            int wl = (j==HS-1) ? 1 : 0;
            gemm_bf16x3<<<gg,256,SM_P1,0>>>(
                hhi+(size_t)cur*HN, hlo+(size_t)cur*HN, HDIM, 0,
                wbhi+(size_t)j*WB, wblo+(size_t)j*WB, 0,
                bblk+(size_t)j*HDIM, 0,
                hhi+(size_t)(cur^1)*HN, hlo+(size_t)(cur^1)*HN, 0, HDIM, HDIM, 1, 1, wl);
            gemm_bf16x3<<<gg,256,SM_P1,sB>>>(
                hhi+(size_t)(2+cur)*HN, hlo+(size_t)(2+cur)*HN, HDIM, 0,
                wbhi+(size_t)j*WB, wblo+(size_t)j*WB, 0,
                bblk+(size_t)j*HDIM, 0,
                hhi+(size_t)(2+(cur^1))*HN, hlo+(size_t)(2+(cur^1))*HN, 0, HDIM, HDIM, 1, 1, wl);
            cur^=1;
        }
        out_proj<<<dim3(BATCH,1,1),256,0,0>>>(hhi, hlo,
            Wout_f+(size_t)i*HDIM*ODIM, bout_f+i*ODIM, tot, phi, plo, i);
        out_proj<<<dim3(BATCH,1,1),256,0,sB>>>(hhi+2ull*HN, hlo+2ull*HN,
            Wout_b+(size_t)i*HDIM*ODIM, bout_b+i*ODIM, tot+(size_t)BATCH*TOTW, phi+PK, plo+PK, i);
    }

    cudaEventRecord(eJoin, sB);
    cudaStreamWaitEvent(0, eJoin, 0);
    attn_final<<<BATCH,128>>>(tot,W1,W2,W3,W4,b4,out);
}